// round 9
// baseline (speedup 1.0000x reference)
#include <cuda_runtime.h>
#include <cuda_bf16.h>
#include <math.h>
#include <stdint.h>

// ---------------- problem constants ----------------
constexpr int NHc = 16;
constexpr int HDc = 64;
constexpr int Kc  = 16;
constexpr int Bc  = 4;
constexpr int Lc  = 2048;
constexpr int Cc  = 1024;      // NH*HD
constexpr int NCc = Lc / Kc;   // 128
constexpr int Mtok = Bc * Lc;  // 8192

// ---------------- scratch (device globals; no allocation allowed) ----------
__device__ float g_q [Bc*Lc*Cc];
__device__ float g_k [Bc*Lc*Cc];
__device__ float g_v [Bc*Lc*Cc];
__device__ float g_xq[Bc*Lc*Cc];   // (b,h,n,k,d)
__device__ float g_xk[Bc*Lc*Cc];
__device__ float g_xv[Bc*Lc*Cc];
__device__ float g_xqw[Bc*Lc*Cc];  // scan output (b,h,n,k,d)
__device__ float g_h2[Bc*Lc*Cc];   // post-norm hidden (b,l,c)
__device__ float g_lr[Bc*NHc*NCc*Kc];
// bf16 split operands for tensor-core GEMMs
__device__ __nv_bfloat16 g_ahi[Bc*Lc*Cc];
__device__ __nv_bfloat16 g_alo[Bc*Lc*Cc];
__device__ __nv_bfloat16 g_whi[4*Cc*Cc];
__device__ __nv_bfloat16 g_wlo[4*Cc*Cc];

// ---------------- helpers ----------------
__device__ __forceinline__ float wsum(float v) {
    #pragma unroll
    for (int o = 16; o; o >>= 1) v += __shfl_xor_sync(0xffffffffu, v, o);
    return v;
}
// MUFU-based tanh: tanh(x) = 1 - 2/(1 + e^{2x}); ex2/rcp rel err ~2^-22.
__device__ __forceinline__ float fast_tanh(float x) {
    float e;
    asm("ex2.approx.f32 %0, %1;" : "=f"(e) : "f"(x * 2.8853900817779268f));
    float r;
    asm("rcp.approx.f32 %0, %1;" : "=f"(r) : "f"(e + 1.0f));
    return fmaf(-2.0f, r, 1.0f);
}
__device__ __forceinline__ float fast_sigmoid(float z) {
    float e;
    asm("ex2.approx.f32 %0, %1;" : "=f"(e) : "f"(-z * 1.4426950408889634f));
    float r;
    asm("rcp.approx.f32 %0, %1;" : "=f"(r) : "f"(e + 1.0f));
    return r;
}
__device__ __forceinline__ float gelu_f(float x) {
    float x2 = x * x;
    float tt = fast_tanh(0.79788456f * x * (1.0f + 0.044715f * x2));
    return 0.5f * x * (1.0f + tt);
}
__device__ __forceinline__ float gelu_bwd_f(float x) {
    float x2 = x * x;
    float tt = fast_tanh(0.79788456f * x * (1.0f + 0.044715f * x2));
    return 0.5f * x * ((1.0f - tt * tt) * (0.79788456f + 0.1070322243f * x2))
         + 0.5f * (1.0f + tt);
}
__device__ __forceinline__ uint32_t smem_u32_of(const void* p) {
    uint32_t a;
    asm("{ .reg .u64 t; cvta.to.shared.u64 t, %1; cvt.u32.u64 %0, t; }" : "=r"(a) : "l"(p));
    return a;
}
__device__ __forceinline__ void cp16(uint32_t dst, const void* src) {
    asm volatile("cp.async.cg.shared.global [%0], [%1], 16;" :: "r"(dst), "l"(src));
}
#define CP_COMMIT() asm volatile("cp.async.commit_group;" ::: "memory")
#define CP_WAIT1()  asm volatile("cp.async.wait_group 1;" ::: "memory")
#define CP_WAIT0()  asm volatile("cp.async.wait_group 0;" ::: "memory")

// ---- packed f32x2 ops ----
__device__ __forceinline__ void fma2(unsigned long long& d, unsigned long long a,
                                     unsigned long long b) {
    asm("fma.rn.f32x2 %0, %1, %2, %0;" : "+l"(d) : "l"(a), "l"(b));
}
__device__ __forceinline__ unsigned long long bcast2(float v) {
    unsigned long long r;
    asm("mov.b64 %0, {%1, %1};" : "=l"(r) : "f"(v));
    return r;
}
__device__ __forceinline__ unsigned long long pack2f(float a, float b) {
    unsigned long long r;
    asm("mov.b64 %0, {%1, %2};" : "=l"(r) : "f"(a), "f"(b));
    return r;
}
__device__ __forceinline__ float2 unpack2(unsigned long long v) {
    float2 r;
    asm("mov.b64 {%0, %1}, %2;" : "=f"(r.x), "=f"(r.y) : "l"(v));
    return r;
}
__device__ __forceinline__ float hsum2(unsigned long long v) {
    float2 p = unpack2(v);
    return p.x + p.y;
}

__device__ __forceinline__ void mma16816(float* c, const uint32_t* a, const uint32_t* b) {
    asm volatile(
        "mma.sync.aligned.m16n8k16.row.col.f32.bf16.bf16.f32 "
        "{%0,%1,%2,%3}, {%4,%5,%6,%7}, {%8,%9}, {%0,%1,%2,%3};"
        : "+f"(c[0]), "+f"(c[1]), "+f"(c[2]), "+f"(c[3])
        : "r"(a[0]), "r"(a[1]), "r"(a[2]), "r"(a[3]), "r"(b[0]), "r"(b[1]));
}
__device__ __forceinline__ void ldsm_x4(uint32_t& r0, uint32_t& r1, uint32_t& r2,
                                        uint32_t& r3, uint32_t addr) {
    asm volatile("ldmatrix.sync.aligned.m8n8.x4.shared.b16 {%0,%1,%2,%3}, [%4];"
                 : "=r"(r0), "=r"(r1), "=r"(r2), "=r"(r3) : "r"(addr));
}

// ---------------- bf16 split kernel: x -> hi + lo ----------------
__global__ __launch_bounds__(256) void split_kernel(const float* __restrict__ src,
                                                    __nv_bfloat16* __restrict__ hi,
                                                    __nv_bfloat16* __restrict__ lo,
                                                    int n4) {
    int i = blockIdx.x * 256 + threadIdx.x;
    if (i >= n4) return;
    float4 v = ((const float4*)src)[i];
    __nv_bfloat16 h0 = __float2bfloat16(v.x), h1 = __float2bfloat16(v.y);
    __nv_bfloat16 h2 = __float2bfloat16(v.z), h3 = __float2bfloat16(v.w);
    __nv_bfloat16 l0 = __float2bfloat16(v.x - __bfloat162float(h0));
    __nv_bfloat16 l1 = __float2bfloat16(v.y - __bfloat162float(h1));
    __nv_bfloat16 l2 = __float2bfloat16(v.z - __bfloat162float(h2));
    __nv_bfloat16 l3 = __float2bfloat16(v.w - __bfloat162float(h3));
    __nv_bfloat162 hA = {h0, h1}, hB = {h2, h3}, lA = {l0, l1}, lB = {l2, l3};
    uint2 hv = {*(uint32_t*)&hA, *(uint32_t*)&hB};
    uint2 lv = {*(uint32_t*)&lA, *(uint32_t*)&lB};
    *(uint2*)(hi + 4 * (size_t)i) = hv;
    *(uint2*)(lo + 4 * (size_t)i) = lv;
}

// ---------------- mma.sync GEMM with ldmatrix fragment loads ----------------
constexpr int SBg = 40;                           // bf16 row stride (80 bytes)
constexpr int TILE_SM = 128 * SBg;
constexpr int GEMM_SMEM = 2 * 4 * TILE_SM * 2;

__global__ __launch_bounds__(256, 1) void mma_gemm_kernel(
    const __nv_bfloat16* __restrict__ Ahi, const __nv_bfloat16* __restrict__ Alo,
    const __nv_bfloat16* __restrict__ Whi, const __nv_bfloat16* __restrict__ Wlo,
    float* __restrict__ outp, int qkv) {
    extern __shared__ __nv_bfloat16 smem[];
    const uint32_t sm0 = smem_u32_of(smem);

    const int t   = threadIdx.x;
    const int wid = t >> 5, l = t & 31;
    const int m0 = blockIdx.y * 128, n0 = blockIdx.x * 128;
    const int wm = (wid & 1) * 64, wn = (wid >> 1) * 32;

    float* dst = qkv ? ((blockIdx.z == 0) ? g_q : (blockIdx.z == 1) ? g_k : g_v) : outp;
    const __nv_bfloat16* wh = Whi + (size_t)blockIdx.z * (Cc * Cc);
    const __nv_bfloat16* wl = Wlo + (size_t)blockIdx.z * (Cc * Cc);

    const __nv_bfloat16* srcs[4] = {Ahi + (size_t)m0 * 1024, Alo + (size_t)m0 * 1024,
                                    wh + (size_t)n0 * 1024,  wl + (size_t)n0 * 1024};

    float acc[4][4][4];
    #pragma unroll
    for (int i = 0; i < 4; i++)
        #pragma unroll
        for (int j = 0; j < 4; j++)
            #pragma unroll
            for (int r = 0; r < 4; r++) acc[i][j][r] = 0.f;

    auto issue = [&](int it, int s) {
        const int k0 = it * 32;
        #pragma unroll
        for (int x = 0; x < 8; x++) {
            int ci = x * 256 + t;
            int tile = ci >> 9, local = ci & 511;
            int row = local >> 2, ch = local & 3;
            const __nv_bfloat16* sp = srcs[tile] + (size_t)row * 1024 + k0 + ch * 8;
            uint32_t dp = sm0 + ((s * 4 + tile) * TILE_SM + row * SBg) * 2 + ch * 16;
            cp16(dp, sp);
        }
    };

    issue(0, 0);
    CP_COMMIT();

    // ldmatrix lane-address components
    const uint32_t a_lane = (uint32_t)(wm + (l & 15)) * 80 + ((l & 16) ? 16 : 0);
    const uint32_t b_lane = (uint32_t)(wn + l) * 80;

    for (int it = 0; it < 32; it++) {
        const int s = it & 1;
        if (it + 1 < 32) issue(it + 1, s ^ 1);
        CP_COMMIT();
        CP_WAIT1();
        __syncthreads();

        const uint32_t tAh = sm0 + (s * 4 + 0) * TILE_SM * 2;
        const uint32_t tAl = sm0 + (s * 4 + 1) * TILE_SM * 2;
        const uint32_t tBh = sm0 + (s * 4 + 2) * TILE_SM * 2;
        const uint32_t tBl = sm0 + (s * 4 + 3) * TILE_SM * 2;

        #pragma unroll
        for (int kk = 0; kk < 2; kk++) {
            const uint32_t kb = kk * 32;
            uint32_t bh[4][2], bl[4][2];
            ldsm_x4(bh[0][0], bh[1][0], bh[2][0], bh[3][0], tBh + b_lane + kb);
            ldsm_x4(bh[0][1], bh[1][1], bh[2][1], bh[3][1], tBh + b_lane + kb + 16);
            ldsm_x4(bl[0][0], bl[1][0], bl[2][0], bl[3][0], tBl + b_lane + kb);
            ldsm_x4(bl[0][1], bl[1][1], bl[2][1], bl[3][1], tBl + b_lane + kb + 16);
            #pragma unroll
            for (int i = 0; i < 4; i++) {
                const uint32_t ao = a_lane + (uint32_t)i * (16 * 80) + kb;
                uint32_t ah[4], al[4];
                ldsm_x4(ah[0], ah[1], ah[2], ah[3], tAh + ao);
                ldsm_x4(al[0], al[1], al[2], al[3], tAl + ao);
                #pragma unroll
                for (int j = 0; j < 4; j++) {
                    mma16816(acc[i][j], ah, bh[j]);
                    mma16816(acc[i][j], ah, bl[j]);
                    mma16816(acc[i][j], al, bh[j]);
                }
            }
        }
        __syncthreads();
    }

    #pragma unroll
    for (int i = 0; i < 4; i++) {
        const int r0 = m0 + wm + i * 16 + (l >> 2);
        #pragma unroll
        for (int j = 0; j < 4; j++) {
            const int c0 = n0 + wn + j * 8 + (l & 3) * 2;
            float2 v0 = make_float2(acc[i][j][0], acc[i][j][1]);
            float2 v1 = make_float2(acc[i][j][2], acc[i][j][3]);
            *(float2*)(dst + (size_t)r0 * 1024 + c0)       = v0;
            *(float2*)(dst + (size_t)(r0 + 8) * 1024 + c0) = v1;
        }
    }
}

// ---------------- prep: ttt_lr sigmoid + RoPE + relayout --------------------
__global__ __launch_bounds__(128) void prep_kernel(const float* __restrict__ hs,
                                                   const float* __restrict__ lrw,
                                                   const float* __restrict__ lrb) {
    const int m  = blockIdx.x;
    const int b  = m >> 11;
    const int l  = m & 2047;
    const int n  = l >> 4, kk = l & 15;
    __shared__ float xrow[1024];
    const int t = threadIdx.x;
    for (int i = t; i < 1024; i += 128) xrow[i] = hs[(size_t)m * 1024 + i];
    __syncthreads();
    const int wp = t >> 5, lane = t & 31;
    #pragma unroll
    for (int s = 0; s < 4; s++) {
        int h = wp * 4 + s;
        float acc = 0.f;
        for (int c = lane; c < 1024; c += 32) acc += xrow[c] * lrw[h * 1024 + c];
        acc = wsum(acc);
        if (lane == 0) {
            float z = acc + lrb[h];
            g_lr[(((size_t)b * NHc + h) * NCc + n) * Kc + kk] = fast_sigmoid(z);
        }
    }
    const float pos = (float)kk;
    for (int pr = t; pr < 512; pr += 128) {
        int h = pr >> 5, i = pr & 31;
        float inv = expf(-(float)(2 * i) * (1.0f / 64.0f) * 9.210340371976184f);
        float sn, cs;
        sincosf(pos * inv, &sn, &cs);
        size_t lin = (size_t)m * 1024 + h * 64 + 2 * i;
        size_t so  = ((((size_t)b * NHc + h) * NCc + n) * Kc + kk) * HDc + 2 * i;
        float qe = g_q[lin], qo = g_q[lin + 1];
        g_xq[so]     = qe * cs - qo * sn;
        g_xq[so + 1] = qo * cs + qe * sn;
        float ke = g_k[lin], ko = g_k[lin + 1];
        g_xk[so]     = ke * cs - ko * sn;
        g_xk[so + 1] = ko * cs + ke * sn;
    }
    for (int i = t; i < 1024; i += 128) {
        int h = i >> 6, d = i & 63;
        g_xv[((((size_t)b * NHc + h) * NCc + n) * Kc + kk) * HDc + d] = g_v[(size_t)m * 1024 + i];
    }
}

// ---------------- scan kernel: 1024 threads, f32x2-packed ------------------
constexpr int O_W1T  = 0;                      // [256][68]  W1T[f][d]
constexpr int O_W2T  = O_W1T + 256 * 68;       // [64][260]  W2T[j][f]
constexpr int O_Z1   = O_W2T + 64 * 260;       // [16][260]  Z1, later X2bar
constexpr int O_X2   = O_Z1 + 16 * 260;        // [16][260]
constexpr int O_GZ1  = O_X2 + 16 * 260;        // [16][260]
constexpr int O_Z2   = O_GZ1 + 16 * 260;       // [16][68]
constexpr int O_Z2B  = O_Z2 + 16 * 68;         // [16][68]
constexpr int O_GZ2T = O_Z2B + 16 * 68;        // [64][20]  gZ2T[j][k]
constexpr int O_A1   = O_GZ2T + 64 * 20;       // [16][20]  (negated)
constexpr int O_A2   = O_A1 + 16 * 20;         // [16][20]  (negated)
constexpr int O_XBUF = O_A2 + 16 * 20;         // 2 stages x {xq,xk,xv} [16][68]
constexpr int XSTAGE = 3 * 16 * 68;            // 3264
constexpr int O_LRS  = O_XBUF + 2 * XSTAGE;    // [2][16]
constexpr int O_TOK  = O_LRS + 32;             // [16]
constexpr int O_B1   = O_TOK + 16;             // [256]
constexpr int O_B2   = O_B1 + 256;             // [64]
constexpr int O_GAM  = O_B2 + 64;              // [64]
constexpr int O_BET  = O_GAM + 64;             // [64]
constexpr int SCAN_SMEM_FLOATS = O_BET + 64;
constexpr int SCAN_SMEM_BYTES  = SCAN_SMEM_FLOATS * 4;   // 230592

__global__ __launch_bounds__(1024, 1) void scan_kernel(
    const float* __restrict__ lti, const float* __restrict__ W1g,
    const float* __restrict__ b1g, const float* __restrict__ W2g,
    const float* __restrict__ b2g, const float* __restrict__ nw,
    const float* __restrict__ nb) {
    extern __shared__ float sm[];
    float* W1T  = sm + O_W1T;
    float* W2T  = sm + O_W2T;
    float* Z1   = sm + O_Z1;
    float* X2   = sm + O_X2;
    float* gZ1  = sm + O_GZ1;
    float* Z2   = sm + O_Z2;
    float* Z2b  = sm + O_Z2B;
    float* gZ2T = sm + O_GZ2T;
    float* A1   = sm + O_A1;
    float* A2   = sm + O_A2;
    float* tok64= sm + O_TOK;
    float* b1s  = sm + O_B1;
    float* b2s  = sm + O_B2;
    float* gam  = sm + O_GAM;
    float* bet  = sm + O_BET;

    const uint32_t sm_u = smem_u32_of(sm);
    const int t  = threadIdx.x;
    const int bh = blockIdx.x;
    const int hh = bh & 15;
    const int wp = t >> 5, lane = t & 31;

    for (int i = t; i < 16384; i += 1024) {
        int d = i >> 8, f = i & 255;
        W1T[f * 68 + d] = W1g[hh * 16384 + d * 256 + f];
    }
    for (int i = t; i < 16384; i += 1024) {
        int f = i >> 6, j = i & 63;
        W2T[j * 260 + f] = W2g[hh * 16384 + f * 64 + j];
    }
    if (t < 256) b1s[t] = b1g[hh * 256 + t];
    if (t < 64) { b2s[t] = b2g[hh * 64 + t]; gam[t] = nw[hh * 64 + t]; bet[t] = nb[hh * 64 + t]; }
    if (t < 16) tok64[t] = fmaxf(1.0f / (float)(t + 1) + lti[t], 0.0f) * (1.0f / 64.0f);

    auto issue_stage = [&](int nn) {
        const int st = nn & 1;
        const size_t cbn = ((size_t)bh * NCc + nn) * (Kc * HDc);
        const uint32_t xbase = sm_u + (O_XBUF + st * XSTAGE) * 4;
        if (t < 772) {
            if (t < 768) {
                int tile = t >> 8, local = t & 255;
                int row = local >> 4, c4 = local & 15;
                const float* srcb = (tile == 0) ? g_xq : (tile == 1) ? g_xk : g_xv;
                cp16(xbase + (tile * 1088 + row * 68 + c4 * 4) * 4,
                     srcb + cbn + row * 64 + c4 * 4);
            } else {
                int q = t - 768;
                cp16(sm_u + (O_LRS + st * 16 + q * 4) * 4,
                     g_lr + ((size_t)bh * NCc + nn) * Kc + q * 4);
            }
        }
    };

    issue_stage(0);
    CP_COMMIT();
    __syncthreads();

    const int colF = t & 255, qF = t >> 8;       // 256-col phases, 4 row-groups
    const int k0F  = qF * 4;
    const int jj64 = t & 63, rg16 = t >> 6;      // 64-col phases, 16 rows
    const int rB = rg16;

    for (int n = 0; n < NCc; n++) {
        const int st = n & 1;
        float* xq_s = sm + O_XBUF + st * XSTAGE;
        float* xk_s = xq_s + 1088;
        float* xv_s = xk_s + 1088;
        float* lrs  = sm + O_LRS + st * 16;
        const size_t cb = ((size_t)bh * NCc + n) * (Kc * HDc);

        if (n + 1 < NCc) { issue_stage(n + 1); CP_COMMIT(); CP_WAIT1(); }
        else             { CP_WAIT0(); }
        __syncthreads();

        // ---- A: Z1 = xk@W1 + b1 ; X2 = gelu(Z1)  (4 rows per thread) ----
        {
            unsigned long long acc[4] = {0ull, 0ull, 0ull, 0ull};
            const float* w1r = W1T + colF * 68;
            #pragma unroll 4
            for (int dg = 0; dg < 16; dg++) {
                ulonglong2 wv = *(const ulonglong2*)(w1r + dg * 4);
                #pragma unroll
                for (int k = 0; k < 4; k++) {
                    ulonglong2 xp = *(const ulonglong2*)(xk_s + (k0F + k) * 68 + dg * 4);
                    fma2(acc[k], xp.x, wv.x);
                    fma2(acc[k], xp.y, wv.y);
                }
            }
            float bv = b1s[colF];
            #pragma unroll
            for (int k = 0; k < 4; k++) {
                float s = hsum2(acc[k]) + bv;
                Z1[(k0F + k) * 260 + colF] = s;
                X2[(k0F + k) * 260 + colF] = gelu_f(s);
            }
        }
        __syncthreads();

        // ---- B: Z2 = X2@W2 + b2 (1 row/thread) ; A1 = -tril(...) ----
        {
            unsigned long long a0 = 0ull, a1 = 0ull;
            const float* w2r = W2T + jj64 * 260;
            const float* x2r = X2 + rB * 260;
            #pragma unroll 8
            for (int fg = 0; fg < 64; fg++) {
                ulonglong2 wv = *(const ulonglong2*)(w2r + fg * 4);
                ulonglong2 x0 = *(const ulonglong2*)(x2r + fg * 4);
                fma2(a0, x0.x, wv.x); fma2(a1, x0.y, wv.y);
            }
            Z2[rB * 68 + jj64] = hsum2(a0) + hsum2(a1) + b2s[jj64];

            if (t < 256) {
                const int ii = t >> 4, jj = t & 15;
                unsigned long long ac = 0ull;
                #pragma unroll 4
                for (int dg = 0; dg < 16; dg++) {
                    ulonglong2 qv = *(const ulonglong2*)(xq_s + ii * 68 + dg * 4);
                    ulonglong2 kv = *(const ulonglong2*)(xk_s + jj * 68 + dg * 4);
                    fma2(ac, qv.x, kv.x); fma2(ac, qv.y, kv.y);
                }
                float s = hsum2(ac);
                A1[ii * 20 + jj] = (jj <= ii) ? -(tok64[ii] * lrs[jj] * (s + 1.0f)) : 0.0f;
            }
        }
        __syncthreads();

        // ---- C: gZ2 = ln_fused_l2_bwd(Z2, xv-xk) -> gZ2T[j][k] ----
        if (wp < 16) {
            int k = wp;
            float z0 = Z2[k * 68 + lane], z1 = Z2[k * 68 + lane + 32];
            float mu = wsum(z0 + z1) * (1.0f / 64.0f);
            float d0 = z0 - mu, d1 = z1 - mu;
            float var = wsum(d0 * d0 + d1 * d1) * (1.0f / 64.0f);
            float rstd = rsqrtf(var + 1e-6f);
            float xh0 = d0 * rstd, xh1 = d1 * rstd;
            float g0 = gam[lane], g1 = gam[lane + 32];
            float be0 = bet[lane], be1 = bet[lane + 32];
            float tg0 = xv_s[k * 68 + lane] - xk_s[k * 68 + lane];
            float tg1 = xv_s[k * 68 + lane + 32] - xk_s[k * 68 + lane + 32];
            float go0 = (g0 * xh0 + be0 - tg0) * g0;
            float go1 = (g1 * xh1 + be1 - tg1) * g1;
            float sgo = wsum(go0 + go1);
            float sgx = wsum(go0 * xh0 + go1 * xh1);
            float cc = rstd * (1.0f / 64.0f);
            gZ2T[lane * 20 + k]        = (64.0f * go0 - sgo - xh0 * sgx) * cc;
            gZ2T[(lane + 32) * 20 + k] = (64.0f * go1 - sgo - xh1 * sgx) * cc;
        }
        __syncthreads();

        // ---- D: gZ1 = (gZ2 @ W2^T) * gelu_bwd(Z1)  (4 rows/thread) ----
        {
            unsigned long long acc[2] = {0ull, 0ull};
            const float* w2c = W2T + colF;
            #pragma unroll 8
            for (int j = 0; j < 64; j++) {
                unsigned long long wpr = bcast2(w2c[j * 260]);
                ulonglong2 ga = *(const ulonglong2*)(gZ2T + j * 20 + k0F);
                fma2(acc[0], ga.x, wpr); fma2(acc[1], ga.y, wpr);
            }
            #pragma unroll
            for (int p = 0; p < 2; p++) {
                float2 g = unpack2(acc[p]);
                int row = k0F + 2 * p;
                gZ1[row * 260 + colF]       = g.x * gelu_bwd_f(Z1[row * 260 + colF]);
                gZ1[(row + 1) * 260 + colF] = g.y * gelu_bwd_f(Z1[(row + 1) * 260 + colF]);
            }
        }
        __syncthreads();

        // ---- E: X2bar = gelu(xq@W1 + b1 + A1neg@gZ1) -> Z1 (4 rows/thread) ----
        {
            unsigned long long acc[4] = {0ull, 0ull, 0ull, 0ull};
            const float* w1r = W1T + colF * 68;
            #pragma unroll 4
            for (int dg = 0; dg < 16; dg++) {
                ulonglong2 wv = *(const ulonglong2*)(w1r + dg * 4);
                #pragma unroll
                for (int k = 0; k < 4; k++) {
                    ulonglong2 xp = *(const ulonglong2*)(xq_s + (k0F + k) * 68 + dg * 4);
                    fma2(acc[k], xp.x, wv.x);
                    fma2(acc[k], xp.y, wv.y);
                }
            }
            #pragma unroll
            for (int jp = 0; jp < 8; jp++) {
                unsigned long long gp = pack2f(gZ1[(2 * jp) * 260 + colF],
                                               gZ1[(2 * jp + 1) * 260 + colF]);
                #pragma unroll
                for (int k = 0; k < 4; k++) {
                    unsigned long long ap =
                        *(const unsigned long long*)(A1 + (k0F + k) * 20 + 2 * jp);
                    fma2(acc[k], ap, gp);
                }
            }
            float bv = b1s[colF];
            #pragma unroll
            for (int k = 0; k < 4; k++) {
                float s = hsum2(acc[k]) + bv;
                Z1[(k0F + k) * 260 + colF] = gelu_f(s);   // X2bar
            }
        }
        __syncthreads();

        // ---- F: A2 = -tril(tok*lr*(X2bar@X2^T + 1)) ----
        if (t < 256) {
            const int ii = t >> 4, jj = t & 15;
            unsigned long long ac = 0ull;
            #pragma unroll 8
            for (int fg = 0; fg < 64; fg++) {
                ulonglong2 zb = *(const ulonglong2*)(Z1 + ii * 260 + fg * 4);
                ulonglong2 xo = *(const ulonglong2*)(X2 + jj * 260 + fg * 4);
                fma2(ac, zb.x, xo.x); fma2(ac, zb.y, xo.y);
            }
            float s = hsum2(ac);
            A2[ii * 20 + jj] = (jj <= ii) ? -(tok64[ii] * lrs[jj] * (s + 1.0f)) : 0.0f;
        }
        __syncthreads();

        // ---- G: Z2b = X2bar@W2 + b2 + A2neg@gZ2  (1 row/thread) ----
        {
            unsigned long long a0 = 0ull, a1 = 0ull;
            const float* w2r = W2T + jj64 * 260;
            const float* zr = Z1 + rB * 260;
            #pragma unroll 8
            for (int fg = 0; fg < 64; fg++) {
                ulonglong2 wv = *(const ulonglong2*)(w2r + fg * 4);
                ulonglong2 x0 = *(const ulonglong2*)(zr + fg * 4);
                fma2(a0, x0.x, wv.x); fma2(a1, x0.y, wv.y);
            }
            #pragma unroll
            for (int jp = 0; jp < 8; jp++) {
                unsigned long long gp =
                    *(const unsigned long long*)(gZ2T + jj64 * 20 + 2 * jp);
                unsigned long long p0 =
                    *(const unsigned long long*)(A2 + rB * 20 + 2 * jp);
                fma2(a0, p0, gp);
            }
            Z2b[rB * 68 + jj64] = hsum2(a0) + hsum2(a1) + b2s[jj64];
        }
        __syncthreads();

        // ---- H: state updates (loop-interchanged, register-lean) ----
        {
            const float lef64 = tok64[15];
            // W1 / b1 : column colF, d-segment d0 = qF*16
            {
                const int d0 = qF * 16;
                float* w1p = W1T + colF * 68 + d0;
                ulonglong2 acc0 = *(const ulonglong2*)(w1p);
                ulonglong2 acc1 = *(const ulonglong2*)(w1p + 4);
                ulonglong2 acc2 = *(const ulonglong2*)(w1p + 8);
                ulonglong2 acc3 = *(const ulonglong2*)(w1p + 12);
                float sb = 0.f;
                #pragma unroll 4
                for (int k = 0; k < 16; k++) {
                    float gck = lef64 * lrs[k] * gZ1[k * 260 + colF];
                    sb += gck;
                    unsigned long long gn = bcast2(-gck);
                    const float* xr = xk_s + k * 68 + d0;
                    ulonglong2 x0 = *(const ulonglong2*)(xr);
                    ulonglong2 x1 = *(const ulonglong2*)(xr + 4);
                    ulonglong2 x2 = *(const ulonglong2*)(xr + 8);
                    ulonglong2 x3 = *(const ulonglong2*)(xr + 12);
                    fma2(acc0.x, x0.x, gn); fma2(acc0.y, x0.y, gn);
                    fma2(acc1.x, x1.x, gn); fma2(acc1.y, x1.y, gn);
                    fma2(acc2.x, x2.x, gn); fma2(acc2.y, x2.y, gn);
                    fma2(acc3.x, x3.x, gn); fma2(acc3.y, x3.y, gn);
                }
                *(ulonglong2*)(w1p)      = acc0;
                *(ulonglong2*)(w1p + 4)  = acc1;
                *(ulonglong2*)(w1p + 8)  = acc2;
                *(ulonglong2*)(w1p + 12) = acc3;
                if (qF == 0) b1s[colF] -= sb;
            }
            // W2 / b2 : row jj64, f-segment f0 = rg16*16
            {
                const int f0 = rg16 * 16;
                float* w2p = W2T + jj64 * 260 + f0;
                ulonglong2 acc0 = *(const ulonglong2*)(w2p);
                ulonglong2 acc1 = *(const ulonglong2*)(w2p + 4);
                ulonglong2 acc2 = *(const ulonglong2*)(w2p + 8);
                ulonglong2 acc3 = *(const ulonglong2*)(w2p + 12);
                float sb2 = 0.f;
                #pragma unroll 4
                for (int k = 0; k < 16; k++) {
                    float hck = lef64 * lrs[k] * gZ2T[jj64 * 20 + k];
                    sb2 += hck;
                    unsigned long long gn = bcast2(-hck);
                    const float* xr = X2 + k * 260 + f0;
                    ulonglong2 x0 = *(const ulonglong2*)(xr);
                    ulonglong2 x1 = *(const ulonglong2*)(xr + 4);
                    ulonglong2 x2 = *(const ulonglong2*)(xr + 8);
                    ulonglong2 x3 = *(const ulonglong2*)(xr + 12);
                    fma2(acc0.x, x0.x, gn); fma2(acc0.y, x0.y, gn);
                    fma2(acc1.x, x1.x, gn); fma2(acc1.y, x1.y, gn);
                    fma2(acc2.x, x2.x, gn); fma2(acc2.y, x2.y, gn);
                    fma2(acc3.x, x3.x, gn); fma2(acc3.y, x3.y, gn);
                }
                *(ulonglong2*)(w2p)      = acc0;
                *(ulonglong2*)(w2p + 4)  = acc1;
                *(ulonglong2*)(w2p + 8)  = acc2;
                *(ulonglong2*)(w2p + 12) = acc3;
                if (rg16 == 0) b2s[jj64] -= sb2;
            }

            // ---- I: out = xq + ln_fwd(Z2b) ----
            if (wp < 16) {
                int k = wp;
                float z0 = Z2b[k * 68 + lane], z1 = Z2b[k * 68 + lane + 32];
                float mu = wsum(z0 + z1) * (1.0f / 64.0f);
                float d0 = z0 - mu, d1 = z1 - mu;
                float var = wsum(d0 * d0 + d1 * d1) * (1.0f / 64.0f);
                float rstd = rsqrtf(var + 1e-6f);
                g_xqw[cb + k * 64 + lane] =
                    gam[lane] * d0 * rstd + bet[lane] + xq_s[k * 68 + lane];
                g_xqw[cb + k * 64 + lane + 32] =
                    gam[lane + 32] * d1 * rstd + bet[lane + 32] + xq_s[k * 68 + lane + 32];
            }
        }
        __syncthreads();
    }
}

// ---------------- post layernorm over C ----------------
__global__ __launch_bounds__(256) void postln_kernel(const float* __restrict__ pw,
                                                     const float* __restrict__ pb) {
    const int m = blockIdx.x;
    const int b = m >> 11, l = m & 2047;
    const int n = l >> 4, kk = l & 15;
    __shared__ float row[1024];
    __shared__ float red[18];
    const int t = threadIdx.x;
    for (int i = t; i < 1024; i += 256) {
        int h = i >> 6, d = i & 63;
        row[i] = g_xqw[((((size_t)b * NHc + h) * NCc + n) * Kc + kk) * HDc + d];
    }
    __syncthreads();
    float s = 0.f, ss = 0.f;
    for (int i = t; i < 1024; i += 256) { float v = row[i]; s += v; ss += v * v; }
    s = wsum(s); ss = wsum(ss);
    const int wp = t >> 5, lane = t & 31;
    if (lane == 0) { red[wp] = s; red[8 + wp] = ss; }
    __syncthreads();
    if (t == 0) {
        float S = 0.f, SS = 0.f;
        for (int w = 0; w < 8; w++) { S += red[w]; SS += red[8 + w]; }
        float mu = S * (1.0f / 1024.0f);
        red[16] = mu;
        red[17] = rsqrtf(SS * (1.0f / 1024.0f) - mu * mu + 1e-6f);
    }
    __syncthreads();
    float mu = red[16], rstd = red[17];
    for (int i = t; i < 1024; i += 256)
        g_h2[(size_t)m * 1024 + i] = pw[i] * (row[i] - mu) * rstd + pb[i];
}

// ---------------- launch ----------------
extern "C" void kernel_launch(void* const* d_in, const int* in_sizes, int n_in,
                              void* d_out, int out_size) {
    (void)in_sizes; (void)n_in; (void)out_size;
    const float* hs  = (const float*)d_in[0];
    const float* wq  = (const float*)d_in[1];
    const float* wk  = (const float*)d_in[2];
    const float* wv  = (const float*)d_in[3];
    const float* wo  = (const float*)d_in[4];
    const float* lti = (const float*)d_in[5];
    const float* lrw = (const float*)d_in[6];
    const float* lrb = (const float*)d_in[7];
    const float* nw  = (const float*)d_in[8];
    const float* nb  = (const float*)d_in[9];
    const float* pw  = (const float*)d_in[10];
    const float* pb  = (const float*)d_in[11];
    const float* W1g = (const float*)d_in[12];
    const float* b1g = (const float*)d_in[13];
    const float* W2g = (const float*)d_in[14];
    const float* b2g = (const float*)d_in[15];
    float* out = (float*)d_out;

    cudaFuncSetAttribute(scan_kernel, cudaFuncAttributeMaxDynamicSharedMemorySize,
                         SCAN_SMEM_BYTES);
    cudaFuncSetAttribute(mma_gemm_kernel, cudaFuncAttributeMaxDynamicSharedMemorySize,
                         GEMM_SMEM);

    void *p_ahi, *p_alo, *p_whi, *p_wlo, *p_h2;
    cudaGetSymbolAddress(&p_ahi, g_ahi);
    cudaGetSymbolAddress(&p_alo, g_alo);
    cudaGetSymbolAddress(&p_whi, g_whi);
    cudaGetSymbolAddress(&p_wlo, g_wlo);
    cudaGetSymbolAddress(&p_h2,  g_h2);
    __nv_bfloat16* ahi = (__nv_bfloat16*)p_ahi;
    __nv_bfloat16* alo = (__nv_bfloat16*)p_alo;
    __nv_bfloat16* whi = (__nv_bfloat16*)p_whi;
    __nv_bfloat16* wlo = (__nv_bfloat16*)p_wlo;

    const int NA4 = (Bc * Lc * Cc) / 4;
    const int NW4 = (Cc * Cc) / 4;

    split_kernel<<<(NA4 + 255) / 256, 256>>>(hs, ahi, alo, NA4);
    split_kernel<<<(NW4 + 255) / 256, 256>>>(wq, whi + 0 * Cc * Cc, wlo + 0 * Cc * Cc, NW4);
    split_kernel<<<(NW4 + 255) / 256, 256>>>(wk, whi + 1 * Cc * Cc, wlo + 1 * Cc * Cc, NW4);
    split_kernel<<<(NW4 + 255) / 256, 256>>>(wv, whi + 2 * Cc * Cc, wlo + 2 * Cc * Cc, NW4);
    split_kernel<<<(NW4 + 255) / 256, 256>>>(wo, whi + 3 * Cc * Cc, wlo + 3 * Cc * Cc, NW4);

    mma_gemm_kernel<<<dim3(8, 64, 3), 256, GEMM_SMEM>>>(ahi, alo, whi, wlo, nullptr, 1);
    prep_kernel<<<Mtok, 128>>>(hs, lrw, lrb);
    scan_kernel<<<Bc * NHc, 1024, SCAN_SMEM_BYTES>>>(lti, W1g, b1g, W2g, b2g, nw, nb);
    postln_kernel<<<Mtok, 256>>>(pw, pb);

    split_kernel<<<(NA4 + 255) / 256, 256>>>((const float*)p_h2, ahi, alo, NA4);
    mma_gemm_kernel<<<dim3(8, 64, 1), 256, GEMM_SMEM>>>(ahi, alo,
                                                        whi + 3 * Cc * Cc, wlo + 3 * Cc * Cc,
                                                        out, 0);
}

// round 11
// speedup vs baseline: 1.1860x; 1.1860x over previous
#include <cuda_runtime.h>
#include <cuda_bf16.h>
#include <math.h>
#include <stdint.h>

// ---------------- problem constants ----------------
constexpr int NHc = 16;
constexpr int HDc = 64;
constexpr int Kc  = 16;
constexpr int Bc  = 4;
constexpr int Lc  = 2048;
constexpr int Cc  = 1024;      // NH*HD
constexpr int NCc = Lc / Kc;   // 128
constexpr int Mtok = Bc * Lc;  // 8192

// ---------------- scratch (device globals; no allocation allowed) ----------
__device__ float g_xq[Bc*Lc*Cc];   // (b,h,n,k,d)
__device__ float g_xk[Bc*Lc*Cc];
__device__ float g_xv[Bc*Lc*Cc];
__device__ float g_xqw[Bc*Lc*Cc];  // scan output (b,h,n,k,d)
__device__ float g_lr[Bc*NHc*NCc*Kc];
__device__ float g_rope_c[Kc*32];  // cos table [kk][i]
__device__ float g_rope_s[Kc*32];  // sin table [kk][i]
// bf16 split operands for tensor-core GEMMs
__device__ __nv_bfloat16 g_ahi[Bc*Lc*Cc];
__device__ __nv_bfloat16 g_alo[Bc*Lc*Cc];
__device__ __nv_bfloat16 g_whi[4*Cc*Cc];
__device__ __nv_bfloat16 g_wlo[4*Cc*Cc];

// ---------------- helpers ----------------
__device__ __forceinline__ float wsum(float v) {
    #pragma unroll
    for (int o = 16; o; o >>= 1) v += __shfl_xor_sync(0xffffffffu, v, o);
    return v;
}
// MUFU-based tanh: tanh(x) = 1 - 2/(1 + e^{2x}); ex2/rcp rel err ~2^-22.
__device__ __forceinline__ float fast_tanh(float x) {
    float e;
    asm("ex2.approx.f32 %0, %1;" : "=f"(e) : "f"(x * 2.8853900817779268f));
    float r;
    asm("rcp.approx.f32 %0, %1;" : "=f"(r) : "f"(e + 1.0f));
    return fmaf(-2.0f, r, 1.0f);
}
__device__ __forceinline__ float fast_sigmoid(float z) {
    float e;
    asm("ex2.approx.f32 %0, %1;" : "=f"(e) : "f"(-z * 1.4426950408889634f));
    float r;
    asm("rcp.approx.f32 %0, %1;" : "=f"(r) : "f"(e + 1.0f));
    return r;
}
__device__ __forceinline__ float gelu_f(float x) {
    float x2 = x * x;
    float tt = fast_tanh(0.79788456f * x * (1.0f + 0.044715f * x2));
    return 0.5f * x * (1.0f + tt);
}
__device__ __forceinline__ float gelu_bwd_f(float x) {
    float x2 = x * x;
    float tt = fast_tanh(0.79788456f * x * (1.0f + 0.044715f * x2));
    return 0.5f * x * ((1.0f - tt * tt) * (0.79788456f + 0.1070322243f * x2))
         + 0.5f * (1.0f + tt);
}
__device__ __forceinline__ uint32_t smem_u32_of(const void* p) {
    uint32_t a;
    asm("{ .reg .u64 t; cvta.to.shared.u64 t, %1; cvt.u32.u64 %0, t; }" : "=r"(a) : "l"(p));
    return a;
}
__device__ __forceinline__ void cp16(uint32_t dst, const void* src) {
    asm volatile("cp.async.cg.shared.global [%0], [%1], 16;" :: "r"(dst), "l"(src));
}
#define CP_COMMIT() asm volatile("cp.async.commit_group;" ::: "memory")
#define CP_WAIT1()  asm volatile("cp.async.wait_group 1;" ::: "memory")
#define CP_WAIT0()  asm volatile("cp.async.wait_group 0;" ::: "memory")

// ---- packed f32x2 ops ----
__device__ __forceinline__ void fma2(unsigned long long& d, unsigned long long a,
                                     unsigned long long b) {
    asm("fma.rn.f32x2 %0, %1, %2, %0;" : "+l"(d) : "l"(a), "l"(b));
}
__device__ __forceinline__ unsigned long long bcast2(float v) {
    unsigned long long r;
    asm("mov.b64 %0, {%1, %1};" : "=l"(r) : "f"(v));
    return r;
}
__device__ __forceinline__ unsigned long long pack2f(float a, float b) {
    unsigned long long r;
    asm("mov.b64 %0, {%1, %2};" : "=l"(r) : "f"(a), "f"(b));
    return r;
}
__device__ __forceinline__ float2 unpack2(unsigned long long v) {
    float2 r;
    asm("mov.b64 {%0, %1}, %2;" : "=f"(r.x), "=f"(r.y) : "l"(v));
    return r;
}
__device__ __forceinline__ float hsum2(unsigned long long v) {
    float2 p = unpack2(v);
    return p.x + p.y;
}

__device__ __forceinline__ void mma16816(float* c, const uint32_t* a, const uint32_t* b) {
    asm volatile(
        "mma.sync.aligned.m16n8k16.row.col.f32.bf16.bf16.f32 "
        "{%0,%1,%2,%3}, {%4,%5,%6,%7}, {%8,%9}, {%0,%1,%2,%3};"
        : "+f"(c[0]), "+f"(c[1]), "+f"(c[2]), "+f"(c[3])
        : "r"(a[0]), "r"(a[1]), "r"(a[2]), "r"(a[3]), "r"(b[0]), "r"(b[1]));
}
__device__ __forceinline__ void ldsm_x4(uint32_t& r0, uint32_t& r1, uint32_t& r2,
                                        uint32_t& r3, uint32_t addr) {
    asm volatile("ldmatrix.sync.aligned.m8n8.x4.shared.b16 {%0,%1,%2,%3}, [%4];"
                 : "=r"(r0), "=r"(r1), "=r"(r2), "=r"(r3) : "r"(addr));
}

// ---------------- rope table (512 distinct angles, full precision) ---------
__global__ void rope_table_kernel() {
    int t = threadIdx.x;           // 512 threads
    int kk = t >> 5, i = t & 31;
    float inv = expf(-(float)(2 * i) * (1.0f / 64.0f) * 9.210340371976184f);
    float sn, cs;
    sincosf((float)kk * inv, &sn, &cs);
    g_rope_c[t] = cs;
    g_rope_s[t] = sn;
}

// ---------------- bf16 split kernel: x -> hi + lo ----------------
__global__ __launch_bounds__(256) void split_kernel(const float* __restrict__ src,
                                                    __nv_bfloat16* __restrict__ hi,
                                                    __nv_bfloat16* __restrict__ lo,
                                                    int n4) {
    int i = blockIdx.x * 256 + threadIdx.x;
    if (i >= n4) return;
    float4 v = ((const float4*)src)[i];
    __nv_bfloat16 h0 = __float2bfloat16(v.x), h1 = __float2bfloat16(v.y);
    __nv_bfloat16 h2 = __float2bfloat16(v.z), h3 = __float2bfloat16(v.w);
    __nv_bfloat16 l0 = __float2bfloat16(v.x - __bfloat162float(h0));
    __nv_bfloat16 l1 = __float2bfloat16(v.y - __bfloat162float(h1));
    __nv_bfloat16 l2 = __float2bfloat16(v.z - __bfloat162float(h2));
    __nv_bfloat16 l3 = __float2bfloat16(v.w - __bfloat162float(h3));
    __nv_bfloat162 hA = {h0, h1}, hB = {h2, h3}, lA = {l0, l1}, lB = {l2, l3};
    uint2 hv = {*(uint32_t*)&hA, *(uint32_t*)&hB};
    uint2 lv = {*(uint32_t*)&lA, *(uint32_t*)&lB};
    *(uint2*)(hi + 4 * (size_t)i) = hv;
    *(uint2*)(lo + 4 * (size_t)i) = lv;
}

// ---------------- mma.sync GEMM + fused RoPE/scatter epilogue --------------
constexpr int SBg = 40;                           // bf16 row stride (80 bytes)
constexpr int TILE_SM = 128 * SBg;
constexpr int GEMM_SMEM = 2 * 4 * TILE_SM * 2;

__global__ __launch_bounds__(256, 1) void mma_gemm_kernel(
    const __nv_bfloat16* __restrict__ Ahi, const __nv_bfloat16* __restrict__ Alo,
    const __nv_bfloat16* __restrict__ Whi, const __nv_bfloat16* __restrict__ Wlo,
    float* __restrict__ outp, int qkv) {
    extern __shared__ __nv_bfloat16 smem[];
    const uint32_t sm0 = smem_u32_of(smem);

    const int t   = threadIdx.x;
    const int wid = t >> 5, l = t & 31;
    const int m0 = blockIdx.y * 128, n0 = blockIdx.x * 128;
    const int wm = (wid & 1) * 64, wn = (wid >> 1) * 32;

    const __nv_bfloat16* wh = Whi + (size_t)blockIdx.z * (Cc * Cc);
    const __nv_bfloat16* wl = Wlo + (size_t)blockIdx.z * (Cc * Cc);

    const __nv_bfloat16* srcs[4] = {Ahi + (size_t)m0 * 1024, Alo + (size_t)m0 * 1024,
                                    wh + (size_t)n0 * 1024,  wl + (size_t)n0 * 1024};

    float acc[4][4][4];
    #pragma unroll
    for (int i = 0; i < 4; i++)
        #pragma unroll
        for (int j = 0; j < 4; j++)
            #pragma unroll
            for (int r = 0; r < 4; r++) acc[i][j][r] = 0.f;

    auto issue = [&](int it, int s) {
        const int k0 = it * 32;
        #pragma unroll
        for (int x = 0; x < 8; x++) {
            int ci = x * 256 + t;
            int tile = ci >> 9, local = ci & 511;
            int row = local >> 2, ch = local & 3;
            const __nv_bfloat16* sp = srcs[tile] + (size_t)row * 1024 + k0 + ch * 8;
            uint32_t dp = sm0 + ((s * 4 + tile) * TILE_SM + row * SBg) * 2 + ch * 16;
            cp16(dp, sp);
        }
    };

    issue(0, 0);
    CP_COMMIT();

    const uint32_t a_lane = (uint32_t)(wm + (l & 15)) * 80 + ((l & 16) ? 16 : 0);
    const uint32_t b_lane = (uint32_t)(wn + l) * 80;

    for (int it = 0; it < 32; it++) {
        const int s = it & 1;
        if (it + 1 < 32) issue(it + 1, s ^ 1);
        CP_COMMIT();
        CP_WAIT1();
        __syncthreads();

        const uint32_t tAh = sm0 + (s * 4 + 0) * TILE_SM * 2;
        const uint32_t tAl = sm0 + (s * 4 + 1) * TILE_SM * 2;
        const uint32_t tBh = sm0 + (s * 4 + 2) * TILE_SM * 2;
        const uint32_t tBl = sm0 + (s * 4 + 3) * TILE_SM * 2;

        #pragma unroll
        for (int kk = 0; kk < 2; kk++) {
            const uint32_t kb = kk * 32;
            uint32_t bh[4][2], bl[4][2];
            ldsm_x4(bh[0][0], bh[1][0], bh[2][0], bh[3][0], tBh + b_lane + kb);
            ldsm_x4(bh[0][1], bh[1][1], bh[2][1], bh[3][1], tBh + b_lane + kb + 16);
            ldsm_x4(bl[0][0], bl[1][0], bl[2][0], bl[3][0], tBl + b_lane + kb);
            ldsm_x4(bl[0][1], bl[1][1], bl[2][1], bl[3][1], tBl + b_lane + kb + 16);
            #pragma unroll
            for (int i = 0; i < 4; i++) {
                const uint32_t ao = a_lane + (uint32_t)i * (16 * 80) + kb;
                uint32_t ah[4], al[4];
                ldsm_x4(ah[0], ah[1], ah[2], ah[3], tAh + ao);
                ldsm_x4(al[0], al[1], al[2], al[3], tAl + ao);
                #pragma unroll
                for (int j = 0; j < 4; j++) {
                    mma16816(acc[i][j], ah, bh[j]);
                    mma16816(acc[i][j], ah, bl[j]);
                    mma16816(acc[i][j], al, bh[j]);
                }
            }
        }
        __syncthreads();
    }

    if (qkv) {
        // fused RoPE (z=0,1) + scatter into scan layout (b,h,n,kk,d)
        const int zz = blockIdx.z;
        float* dst3 = (zz == 0) ? g_xq : (zz == 1) ? g_xk : g_xv;
        #pragma unroll
        for (int i = 0; i < 4; i++) {
            const int rbase = m0 + wm + i * 16 + (l >> 2);
            #pragma unroll
            for (int rr = 0; rr < 2; rr++) {
                const int r = rbase + rr * 8;
                const int b = r >> 11;
                const int n = (r & 2047) >> 4;
                const int kk = r & 15;
                #pragma unroll
                for (int j = 0; j < 4; j++) {
                    const int c0 = n0 + wn + j * 8 + (l & 3) * 2;
                    const int h = c0 >> 6, d = c0 & 63;
                    float vx = acc[i][j][rr * 2 + 0];
                    float vy = acc[i][j][rr * 2 + 1];
                    if (zz < 2) {
                        const int ti = kk * 32 + (d >> 1);
                        float cs = g_rope_c[ti], sn = g_rope_s[ti];
                        float e = vx * cs - vy * sn;
                        float o = vy * cs + vx * sn;
                        vx = e; vy = o;
                    }
                    size_t off = ((((size_t)b * NHc + h) * NCc + n) * Kc + kk) * HDc + d;
                    *(float2*)(dst3 + off) = make_float2(vx, vy);
                }
            }
        }
    } else {
        #pragma unroll
        for (int i = 0; i < 4; i++) {
            const int r0 = m0 + wm + i * 16 + (l >> 2);
            #pragma unroll
            for (int j = 0; j < 4; j++) {
                const int c0 = n0 + wn + j * 8 + (l & 3) * 2;
                float2 v0 = make_float2(acc[i][j][0], acc[i][j][1]);
                float2 v1 = make_float2(acc[i][j][2], acc[i][j][3]);
                *(float2*)(outp + (size_t)r0 * 1024 + c0)       = v0;
                *(float2*)(outp + (size_t)(r0 + 8) * 1024 + c0) = v1;
            }
        }
    }
}

// ---------------- prep: ttt_lr sigmoid only --------------------------------
__global__ __launch_bounds__(128) void prep_kernel(const float* __restrict__ hs,
                                                   const float* __restrict__ lrw,
                                                   const float* __restrict__ lrb) {
    const int m  = blockIdx.x;
    const int b  = m >> 11;
    const int l  = m & 2047;
    const int n  = l >> 4, kk = l & 15;
    __shared__ float xrow[1024];
    const int t = threadIdx.x;
    for (int i = t; i < 1024; i += 128) xrow[i] = hs[(size_t)m * 1024 + i];
    __syncthreads();
    const int wp = t >> 5, lane = t & 31;
    #pragma unroll
    for (int s = 0; s < 4; s++) {
        int h = wp * 4 + s;
        float acc = 0.f;
        for (int c = lane; c < 1024; c += 32) acc += xrow[c] * lrw[h * 1024 + c];
        acc = wsum(acc);
        if (lane == 0) {
            float z = acc + lrb[h];
            g_lr[(((size_t)b * NHc + h) * NCc + n) * Kc + kk] = fast_sigmoid(z);
        }
    }
}

// ---------------- scan kernel: 512 threads, f32x2-packed (R7 best) ---------
constexpr int O_W1T  = 0;                      // [256][68]  W1T[f][d]
constexpr int O_W2T  = O_W1T + 256 * 68;       // [64][260]  W2T[j][f]
constexpr int O_Z1   = O_W2T + 64 * 260;       // [16][260]  Z1, later X2bar
constexpr int O_X2   = O_Z1 + 16 * 260;        // [16][260]
constexpr int O_GZ1  = O_X2 + 16 * 260;        // [16][260]
constexpr int O_Z2   = O_GZ1 + 16 * 260;       // [16][68]
constexpr int O_Z2B  = O_Z2 + 16 * 68;         // [16][68]
constexpr int O_GZ2T = O_Z2B + 16 * 68;        // [64][20]  gZ2T[j][k]
constexpr int O_A1   = O_GZ2T + 64 * 20;       // [16][20]  (negated)
constexpr int O_A2   = O_A1 + 16 * 20;         // [16][20]  (negated)
constexpr int O_XBUF = O_A2 + 16 * 20;         // 2 stages x {xq,xk,xv} [16][68]
constexpr int XSTAGE = 3 * 16 * 68;            // 3264
constexpr int O_LRS  = O_XBUF + 2 * XSTAGE;    // [2][16]
constexpr int O_TOK  = O_LRS + 32;             // [16]
constexpr int O_B1   = O_TOK + 16;             // [256]
constexpr int O_B2   = O_B1 + 256;             // [64]
constexpr int O_GAM  = O_B2 + 64;              // [64]
constexpr int O_BET  = O_GAM + 64;             // [64]
constexpr int SCAN_SMEM_FLOATS = O_BET + 64;
constexpr int SCAN_SMEM_BYTES  = SCAN_SMEM_FLOATS * 4;   // 230592

__global__ __launch_bounds__(512, 1) void scan_kernel(
    const float* __restrict__ lti, const float* __restrict__ W1g,
    const float* __restrict__ b1g, const float* __restrict__ W2g,
    const float* __restrict__ b2g, const float* __restrict__ nw,
    const float* __restrict__ nb) {
    extern __shared__ float sm[];
    float* W1T  = sm + O_W1T;
    float* W2T  = sm + O_W2T;
    float* Z1   = sm + O_Z1;
    float* X2   = sm + O_X2;
    float* gZ1  = sm + O_GZ1;
    float* Z2   = sm + O_Z2;
    float* Z2b  = sm + O_Z2B;
    float* gZ2T = sm + O_GZ2T;
    float* A1   = sm + O_A1;
    float* A2   = sm + O_A2;
    float* tok64= sm + O_TOK;
    float* b1s  = sm + O_B1;
    float* b2s  = sm + O_B2;
    float* gam  = sm + O_GAM;
    float* bet  = sm + O_BET;

    const uint32_t sm_u = smem_u32_of(sm);
    const int t  = threadIdx.x;
    const int bh = blockIdx.x;
    const int hh = bh & 15;
    const int wp = t >> 5, lane = t & 31;

    for (int i = t; i < 16384; i += 512) {
        int d = i >> 8, f = i & 255;
        W1T[f * 68 + d] = W1g[hh * 16384 + d * 256 + f];
    }
    for (int i = t; i < 16384; i += 512) {
        int f = i >> 6, j = i & 63;
        W2T[j * 260 + f] = W2g[hh * 16384 + f * 64 + j];
    }
    if (t < 256) b1s[t] = b1g[hh * 256 + t];
    if (t < 64) { b2s[t] = b2g[hh * 64 + t]; gam[t] = nw[hh * 64 + t]; bet[t] = nb[hh * 64 + t]; }
    if (t < 16) tok64[t] = fmaxf(1.0f / (float)(t + 1) + lti[t], 0.0f) * (1.0f / 64.0f);

    auto issue_stage = [&](int nn) {
        const int st = nn & 1;
        const size_t cbn = ((size_t)bh * NCc + nn) * (Kc * HDc);
        const uint32_t xbase = sm_u + (O_XBUF + st * XSTAGE) * 4;
        for (int i = t; i < 772; i += 512) {
            if (i < 768) {
                int tile = i >> 8, local = i & 255;
                int row = local >> 4, c4 = local & 15;
                const float* srcb = (tile == 0) ? g_xq : (tile == 1) ? g_xk : g_xv;
                cp16(xbase + (tile * 1088 + row * 68 + c4 * 4) * 4,
                     srcb + cbn + row * 64 + c4 * 4);
            } else {
                int q = i - 768;
                cp16(sm_u + (O_LRS + st * 16 + q * 4) * 4,
                     g_lr + ((size_t)bh * NCc + nn) * Kc + q * 4);
            }
        }
    };

    issue_stage(0);
    CP_COMMIT();
    __syncthreads();

    const int colF = t & 255, halfF = t >> 8;
    const int k0F  = halfF * 8;
    const int jj64 = t & 63, rg = t >> 6;
    const int r0 = rg * 2;

    for (int n = 0; n < NCc; n++) {
        const int st = n & 1;
        float* xq_s = sm + O_XBUF + st * XSTAGE;
        float* xk_s = xq_s + 1088;
        float* xv_s = xk_s + 1088;
        float* lrs  = sm + O_LRS + st * 16;
        const size_t cb = ((size_t)bh * NCc + n) * (Kc * HDc);

        if (n + 1 < NCc) { issue_stage(n + 1); CP_COMMIT(); CP_WAIT1(); }
        else             { CP_WAIT0(); }
        __syncthreads();

        // ---- A: Z1 = xk@W1 + b1 ; X2 = gelu(Z1) ----
        {
            unsigned long long acc[8];
            #pragma unroll
            for (int k = 0; k < 8; k++) acc[k] = 0ull;
            const float* w1r = W1T + colF * 68;
            #pragma unroll 4
            for (int dg = 0; dg < 16; dg++) {
                ulonglong2 wv = *(const ulonglong2*)(w1r + dg * 4);
                #pragma unroll
                for (int k = 0; k < 8; k++) {
                    ulonglong2 xp = *(const ulonglong2*)(xk_s + (k0F + k) * 68 + dg * 4);
                    fma2(acc[k], xp.x, wv.x);
                    fma2(acc[k], xp.y, wv.y);
                }
            }
            float bv = b1s[colF];
            #pragma unroll
            for (int k = 0; k < 8; k++) {
                float s = hsum2(acc[k]) + bv;
                Z1[(k0F + k) * 260 + colF] = s;
                X2[(k0F + k) * 260 + colF] = gelu_f(s);
            }
        }
        __syncthreads();

        // ---- B: Z2 = X2@W2 + b2 ; A1 = -tril(tok*lr*(xq@xk^T + 1)) ----
        {
            unsigned long long a0 = 0ull, a1 = 0ull;
            const float* w2r = W2T + jj64 * 260;
            #pragma unroll 8
            for (int fg = 0; fg < 64; fg++) {
                ulonglong2 wv = *(const ulonglong2*)(w2r + fg * 4);
                ulonglong2 x0 = *(const ulonglong2*)(X2 + r0 * 260 + fg * 4);
                ulonglong2 x1 = *(const ulonglong2*)(X2 + (r0 + 1) * 260 + fg * 4);
                fma2(a0, x0.x, wv.x); fma2(a0, x0.y, wv.y);
                fma2(a1, x1.x, wv.x); fma2(a1, x1.y, wv.y);
            }
            float bv = b2s[jj64];
            Z2[r0 * 68 + jj64]       = hsum2(a0) + bv;
            Z2[(r0 + 1) * 68 + jj64] = hsum2(a1) + bv;

            if (t < 256) {
                const int ii = t >> 4, jj = t & 15;
                unsigned long long ac = 0ull;
                #pragma unroll 4
                for (int dg = 0; dg < 16; dg++) {
                    ulonglong2 qv = *(const ulonglong2*)(xq_s + ii * 68 + dg * 4);
                    ulonglong2 kv = *(const ulonglong2*)(xk_s + jj * 68 + dg * 4);
                    fma2(ac, qv.x, kv.x); fma2(ac, qv.y, kv.y);
                }
                float s = hsum2(ac);
                A1[ii * 20 + jj] = (jj <= ii) ? -(tok64[ii] * lrs[jj] * (s + 1.0f)) : 0.0f;
            }
        }
        __syncthreads();

        // ---- C: gZ2 = ln_fused_l2_bwd(Z2, xv-xk) -> gZ2T[j][k] ----
        {
            int k = wp;
            float z0 = Z2[k * 68 + lane], z1 = Z2[k * 68 + lane + 32];
            float mu = wsum(z0 + z1) * (1.0f / 64.0f);
            float d0 = z0 - mu, d1 = z1 - mu;
            float var = wsum(d0 * d0 + d1 * d1) * (1.0f / 64.0f);
            float rstd = rsqrtf(var + 1e-6f);
            float xh0 = d0 * rstd, xh1 = d1 * rstd;
            float g0 = gam[lane], g1 = gam[lane + 32];
            float be0 = bet[lane], be1 = bet[lane + 32];
            float tg0 = xv_s[k * 68 + lane] - xk_s[k * 68 + lane];
            float tg1 = xv_s[k * 68 + lane + 32] - xk_s[k * 68 + lane + 32];
            float go0 = (g0 * xh0 + be0 - tg0) * g0;
            float go1 = (g1 * xh1 + be1 - tg1) * g1;
            float sgo = wsum(go0 + go1);
            float sgx = wsum(go0 * xh0 + go1 * xh1);
            float cc = rstd * (1.0f / 64.0f);
            gZ2T[lane * 20 + k]        = (64.0f * go0 - sgo - xh0 * sgx) * cc;
            gZ2T[(lane + 32) * 20 + k] = (64.0f * go1 - sgo - xh1 * sgx) * cc;
        }
        __syncthreads();

        // ---- D: gZ1 = (gZ2 @ W2^T) * gelu_bwd(Z1) ----
        {
            unsigned long long acc[4] = {0ull, 0ull, 0ull, 0ull};
            const float* w2c = W2T + colF;
            #pragma unroll 8
            for (int j = 0; j < 64; j++) {
                unsigned long long wpr = bcast2(w2c[j * 260]);
                ulonglong2 ga = *(const ulonglong2*)(gZ2T + j * 20 + k0F);
                ulonglong2 gb = *(const ulonglong2*)(gZ2T + j * 20 + k0F + 4);
                fma2(acc[0], ga.x, wpr); fma2(acc[1], ga.y, wpr);
                fma2(acc[2], gb.x, wpr); fma2(acc[3], gb.y, wpr);
            }
            #pragma unroll
            for (int p = 0; p < 4; p++) {
                float2 g = unpack2(acc[p]);
                int row = k0F + 2 * p;
                gZ1[row * 260 + colF]       = g.x * gelu_bwd_f(Z1[row * 260 + colF]);
                gZ1[(row + 1) * 260 + colF] = g.y * gelu_bwd_f(Z1[(row + 1) * 260 + colF]);
            }
        }
        __syncthreads();

        // ---- E: X2bar = gelu(xq@W1 + b1 + A1neg@gZ1) -> Z1 buffer ----
        {
            unsigned long long acc[8];
            #pragma unroll
            for (int k = 0; k < 8; k++) acc[k] = 0ull;
            const float* w1r = W1T + colF * 68;
            #pragma unroll 4
            for (int dg = 0; dg < 16; dg++) {
                ulonglong2 wv = *(const ulonglong2*)(w1r + dg * 4);
                #pragma unroll
                for (int k = 0; k < 8; k++) {
                    ulonglong2 xp = *(const ulonglong2*)(xq_s + (k0F + k) * 68 + dg * 4);
                    fma2(acc[k], xp.x, wv.x);
                    fma2(acc[k], xp.y, wv.y);
                }
            }
            #pragma unroll
            for (int jp = 0; jp < 8; jp++) {
                unsigned long long gp = pack2f(gZ1[(2 * jp) * 260 + colF],
                                               gZ1[(2 * jp + 1) * 260 + colF]);
                #pragma unroll
                for (int k = 0; k < 8; k++) {
                    unsigned long long ap =
                        *(const unsigned long long*)(A1 + (k0F + k) * 20 + 2 * jp);
                    fma2(acc[k], ap, gp);
                }
            }
            float bv = b1s[colF];
            #pragma unroll
            for (int k = 0; k < 8; k++) {
                float s = hsum2(acc[k]) + bv;
                Z1[(k0F + k) * 260 + colF] = gelu_f(s);   // X2bar
            }
        }
        __syncthreads();

        // ---- F: A2 = -tril(tok*lr*(X2bar@X2^T + 1)) ----
        if (t < 256) {
            const int ii = t >> 4, jj = t & 15;
            unsigned long long ac = 0ull;
            #pragma unroll 8
            for (int fg = 0; fg < 64; fg++) {
                ulonglong2 zb = *(const ulonglong2*)(Z1 + ii * 260 + fg * 4);
                ulonglong2 xo = *(const ulonglong2*)(X2 + jj * 260 + fg * 4);
                fma2(ac, zb.x, xo.x); fma2(ac, zb.y, xo.y);
            }
            float s = hsum2(ac);
            A2[ii * 20 + jj] = (jj <= ii) ? -(tok64[ii] * lrs[jj] * (s + 1.0f)) : 0.0f;
        }
        __syncthreads();

        // ---- G: Z2b = X2bar@W2 + b2 + A2neg@gZ2 ----
        {
            unsigned long long a0 = 0ull, a1 = 0ull;
            const float* w2r = W2T + jj64 * 260;
            #pragma unroll 8
            for (int fg = 0; fg < 64; fg++) {
                ulonglong2 wv = *(const ulonglong2*)(w2r + fg * 4);
                ulonglong2 x0 = *(const ulonglong2*)(Z1 + r0 * 260 + fg * 4);
                ulonglong2 x1 = *(const ulonglong2*)(Z1 + (r0 + 1) * 260 + fg * 4);
                fma2(a0, x0.x, wv.x); fma2(a0, x0.y, wv.y);
                fma2(a1, x1.x, wv.x); fma2(a1, x1.y, wv.y);
            }
            #pragma unroll
            for (int jp = 0; jp < 8; jp++) {
                unsigned long long gp =
                    *(const unsigned long long*)(gZ2T + jj64 * 20 + 2 * jp);
                unsigned long long p0 =
                    *(const unsigned long long*)(A2 + r0 * 20 + 2 * jp);
                unsigned long long p1 =
                    *(const unsigned long long*)(A2 + (r0 + 1) * 20 + 2 * jp);
                fma2(a0, p0, gp);
                fma2(a1, p1, gp);
            }
            float bv = b2s[jj64];
            Z2b[r0 * 68 + jj64]       = hsum2(a0) + bv;
            Z2b[(r0 + 1) * 68 + jj64] = hsum2(a1) + bv;
        }
        __syncthreads();

        // ---- H: state updates ----
        {
            const float lef64 = tok64[15];
            {
                const int d0 = halfF * 32;
                float gc[16]; float sb = 0.f;
                #pragma unroll
                for (int k = 0; k < 16; k++) {
                    gc[k] = lef64 * lrs[k] * gZ1[k * 260 + colF];
                    sb += gc[k];
                }
                if (halfF == 0) b1s[colF] -= sb;
                unsigned long long gneg[16];
                #pragma unroll
                for (int k = 0; k < 16; k++) gneg[k] = bcast2(-gc[k]);
                float* w1r = W1T + colF * 68 + d0;
                #pragma unroll
                for (int dg = 0; dg < 8; dg++) {
                    ulonglong2 acc = *(const ulonglong2*)(w1r + dg * 4);
                    #pragma unroll
                    for (int k = 0; k < 16; k++) {
                        ulonglong2 xp = *(const ulonglong2*)(xk_s + k * 68 + d0 + dg * 4);
                        fma2(acc.x, xp.x, gneg[k]);
                        fma2(acc.y, xp.y, gneg[k]);
                    }
                    *(ulonglong2*)(w1r + dg * 4) = acc;
                }
            }
            {
                const int f0 = rg * 32;
                float hc[16]; float sb2 = 0.f;
                #pragma unroll
                for (int k = 0; k < 16; k++) {
                    hc[k] = lef64 * lrs[k] * gZ2T[jj64 * 20 + k];
                    sb2 += hc[k];
                }
                if (rg == 0) b2s[jj64] -= sb2;
                unsigned long long hneg[16];
                #pragma unroll
                for (int k = 0; k < 16; k++) hneg[k] = bcast2(-hc[k]);
                float* w2r = W2T + jj64 * 260 + f0;
                #pragma unroll
                for (int fg = 0; fg < 8; fg++) {
                    ulonglong2 acc = *(const ulonglong2*)(w2r + fg * 4);
                    #pragma unroll
                    for (int k = 0; k < 16; k++) {
                        ulonglong2 xp = *(const ulonglong2*)(X2 + k * 260 + f0 + fg * 4);
                        fma2(acc.x, xp.x, hneg[k]);
                        fma2(acc.y, xp.y, hneg[k]);
                    }
                    *(ulonglong2*)(w2r + fg * 4) = acc;
                }
            }

            // ---- I: out = xq + ln_fwd(Z2b) ----
            {
                int k = wp;
                float z0 = Z2b[k * 68 + lane], z1 = Z2b[k * 68 + lane + 32];
                float mu = wsum(z0 + z1) * (1.0f / 64.0f);
                float d0 = z0 - mu, d1 = z1 - mu;
                float var = wsum(d0 * d0 + d1 * d1) * (1.0f / 64.0f);
                float rstd = rsqrtf(var + 1e-6f);
                g_xqw[cb + k * 64 + lane] =
                    gam[lane] * d0 * rstd + bet[lane] + xq_s[k * 68 + lane];
                g_xqw[cb + k * 64 + lane + 32] =
                    gam[lane + 32] * d1 * rstd + bet[lane + 32] + xq_s[k * 68 + lane + 32];
            }
        }
        __syncthreads();
    }
}

// ---------------- post layernorm over C (fused bf16 split output) ----------
__global__ __launch_bounds__(256) void postln_kernel(const float* __restrict__ pw,
                                                     const float* __restrict__ pb,
                                                     __nv_bfloat16* __restrict__ ahi,
                                                     __nv_bfloat16* __restrict__ alo) {
    const int m = blockIdx.x;
    const int b = m >> 11, l = m & 2047;
    const int n = l >> 4, kk = l & 15;
    __shared__ float row[1024];
    __shared__ float red[18];
    const int t = threadIdx.x;
    for (int i = t; i < 1024; i += 256) {
        int h = i >> 6, d = i & 63;
        row[i] = g_xqw[((((size_t)b * NHc + h) * NCc + n) * Kc + kk) * HDc + d];
    }
    __syncthreads();
    float s = 0.f, ss = 0.f;
    for (int i = t; i < 1024; i += 256) { float v = row[i]; s += v; ss += v * v; }
    s = wsum(s); ss = wsum(ss);
    const int wp = t >> 5, lane = t & 31;
    if (lane == 0) { red[wp] = s; red[8 + wp] = ss; }
    __syncthreads();
    if (t == 0) {
        float S = 0.f, SS = 0.f;
        for (int w = 0; w < 8; w++) { S += red[w]; SS += red[8 + w]; }
        float mu = S * (1.0f / 1024.0f);
        red[16] = mu;
        red[17] = rsqrtf(SS * (1.0f / 1024.0f) - mu * mu + 1e-6f);
    }
    __syncthreads();
    float mu = red[16], rstd = red[17];
    for (int i = t; i < 1024; i += 256) {
        float v = pw[i] * (row[i] - mu) * rstd + pb[i];
        __nv_bfloat16 hv = __float2bfloat16(v);
        ahi[(size_t)m * 1024 + i] = hv;
        alo[(size_t)m * 1024 + i] = __float2bfloat16(v - __bfloat162float(hv));
    }
}

// ---------------- launch ----------------
extern "C" void kernel_launch(void* const* d_in, const int* in_sizes, int n_in,
                              void* d_out, int out_size) {
    (void)in_sizes; (void)n_in; (void)out_size;
    const float* hs  = (const float*)d_in[0];
    const float* wq  = (const float*)d_in[1];
    const float* wk  = (const float*)d_in[2];
    const float* wv  = (const float*)d_in[3];
    const float* wo  = (const float*)d_in[4];
    const float* lti = (const float*)d_in[5];
    const float* lrw = (const float*)d_in[6];
    const float* lrb = (const float*)d_in[7];
    const float* nw  = (const float*)d_in[8];
    const float* nb  = (const float*)d_in[9];
    const float* pw  = (const float*)d_in[10];
    const float* pb  = (const float*)d_in[11];
    const float* W1g = (const float*)d_in[12];
    const float* b1g = (const float*)d_in[13];
    const float* W2g = (const float*)d_in[14];
    const float* b2g = (const float*)d_in[15];
    float* out = (float*)d_out;

    cudaFuncSetAttribute(scan_kernel, cudaFuncAttributeMaxDynamicSharedMemorySize,
                         SCAN_SMEM_BYTES);
    cudaFuncSetAttribute(mma_gemm_kernel, cudaFuncAttributeMaxDynamicSharedMemorySize,
                         GEMM_SMEM);

    void *p_ahi, *p_alo, *p_whi, *p_wlo;
    cudaGetSymbolAddress(&p_ahi, g_ahi);
    cudaGetSymbolAddress(&p_alo, g_alo);
    cudaGetSymbolAddress(&p_whi, g_whi);
    cudaGetSymbolAddress(&p_wlo, g_wlo);
    __nv_bfloat16* ahi = (__nv_bfloat16*)p_ahi;
    __nv_bfloat16* alo = (__nv_bfloat16*)p_alo;
    __nv_bfloat16* whi = (__nv_bfloat16*)p_whi;
    __nv_bfloat16* wlo = (__nv_bfloat16*)p_wlo;

    const int NA4 = (Bc * Lc * Cc) / 4;
    const int NW4 = (Cc * Cc) / 4;

    rope_table_kernel<<<1, 512>>>();
    split_kernel<<<(NA4 + 255) / 256, 256>>>(hs, ahi, alo, NA4);
    split_kernel<<<(NW4 + 255) / 256, 256>>>(wq, whi + 0 * Cc * Cc, wlo + 0 * Cc * Cc, NW4);
    split_kernel<<<(NW4 + 255) / 256, 256>>>(wk, whi + 1 * Cc * Cc, wlo + 1 * Cc * Cc, NW4);
    split_kernel<<<(NW4 + 255) / 256, 256>>>(wv, whi + 2 * Cc * Cc, wlo + 2 * Cc * Cc, NW4);
    split_kernel<<<(NW4 + 255) / 256, 256>>>(wo, whi + 3 * Cc * Cc, wlo + 3 * Cc * Cc, NW4);

    prep_kernel<<<Mtok, 128>>>(hs, lrw, lrb);
    mma_gemm_kernel<<<dim3(8, 64, 3), 256, GEMM_SMEM>>>(ahi, alo, whi, wlo, nullptr, 1);
    scan_kernel<<<Bc * NHc, 512, SCAN_SMEM_BYTES>>>(lti, W1g, b1g, W2g, b2g, nw, nb);
    postln_kernel<<<Mtok, 256>>>(pw, pb, ahi, alo);
    mma_gemm_kernel<<<dim3(8, 64, 1), 256, GEMM_SMEM>>>(ahi, alo,
                                                        whi + 3 * Cc * Cc, wlo + 3 * Cc * Cc,
                                                        out, 0);
}

// round 13
// speedup vs baseline: 1.1863x; 1.0002x over previous
#include <cuda_runtime.h>
#include <cuda_bf16.h>
#include <math.h>
#include <stdint.h>

// ---------------- problem constants ----------------
constexpr int NHc = 16;
constexpr int HDc = 64;
constexpr int Kc  = 16;
constexpr int Bc  = 4;
constexpr int Lc  = 2048;
constexpr int Cc  = 1024;      // NH*HD
constexpr int NCc = Lc / Kc;   // 128
constexpr int Mtok = Bc * Lc;  // 8192

// ---------------- scratch (device globals; no allocation allowed) ----------
__device__ float g_xq[Bc*Lc*Cc];   // (b,h,n,k,d)
__device__ float g_xk[Bc*Lc*Cc];
__device__ float g_xv[Bc*Lc*Cc];
__device__ float g_xqw[Bc*Lc*Cc];  // scan output (b,h,n,k,d)
__device__ float g_lr[Bc*NHc*NCc*Kc];
__device__ float g_rope_c[Kc*32];  // cos table [kk][i]
__device__ float g_rope_s[Kc*32];  // sin table [kk][i]
// bf16 split operands for tensor-core GEMMs
__device__ __nv_bfloat16 g_ahi[Bc*Lc*Cc];
__device__ __nv_bfloat16 g_alo[Bc*Lc*Cc];
__device__ __nv_bfloat16 g_whi[4*Cc*Cc];
__device__ __nv_bfloat16 g_wlo[4*Cc*Cc];

// ---------------- helpers ----------------
__device__ __forceinline__ float wsum(float v) {
    #pragma unroll
    for (int o = 16; o; o >>= 1) v += __shfl_xor_sync(0xffffffffu, v, o);
    return v;
}
// MUFU-based tanh: tanh(x) = 1 - 2/(1 + e^{2x}); ex2/rcp rel err ~2^-22.
__device__ __forceinline__ float fast_tanh(float x) {
    float e;
    asm("ex2.approx.f32 %0, %1;" : "=f"(e) : "f"(x * 2.8853900817779268f));
    float r;
    asm("rcp.approx.f32 %0, %1;" : "=f"(r) : "f"(e + 1.0f));
    return fmaf(-2.0f, r, 1.0f);
}
__device__ __forceinline__ float fast_sigmoid(float z) {
    float e;
    asm("ex2.approx.f32 %0, %1;" : "=f"(e) : "f"(-z * 1.4426950408889634f));
    float r;
    asm("rcp.approx.f32 %0, %1;" : "=f"(r) : "f"(e + 1.0f));
    return r;
}
__device__ __forceinline__ float gelu_f(float x) {
    float x2 = x * x;
    float tt = fast_tanh(0.79788456f * x * (1.0f + 0.044715f * x2));
    return 0.5f * x * (1.0f + tt);
}
__device__ __forceinline__ float gelu_bwd_f(float x) {
    float x2 = x * x;
    float tt = fast_tanh(0.79788456f * x * (1.0f + 0.044715f * x2));
    return 0.5f * x * ((1.0f - tt * tt) * (0.79788456f + 0.1070322243f * x2))
         + 0.5f * (1.0f + tt);
}
__device__ __forceinline__ uint32_t smem_u32_of(const void* p) {
    uint32_t a;
    asm("{ .reg .u64 t; cvta.to.shared.u64 t, %1; cvt.u32.u64 %0, t; }" : "=r"(a) : "l"(p));
    return a;
}
__device__ __forceinline__ void cp16(uint32_t dst, const void* src) {
    asm volatile("cp.async.cg.shared.global [%0], [%1], 16;" :: "r"(dst), "l"(src));
}
#define CP_COMMIT() asm volatile("cp.async.commit_group;" ::: "memory")
#define CP_WAIT1()  asm volatile("cp.async.wait_group 1;" ::: "memory")
#define CP_WAIT0()  asm volatile("cp.async.wait_group 0;" ::: "memory")

// ---- packed f32x2 ops ----
__device__ __forceinline__ void fma2(unsigned long long& d, unsigned long long a,
                                     unsigned long long b) {
    asm("fma.rn.f32x2 %0, %1, %2, %0;" : "+l"(d) : "l"(a), "l"(b));
}
__device__ __forceinline__ unsigned long long bcast2(float v) {
    unsigned long long r;
    asm("mov.b64 %0, {%1, %1};" : "=l"(r) : "f"(v));
    return r;
}
__device__ __forceinline__ unsigned long long pack2f(float a, float b) {
    unsigned long long r;
    asm("mov.b64 %0, {%1, %2};" : "=l"(r) : "f"(a), "f"(b));
    return r;
}
__device__ __forceinline__ float2 unpack2(unsigned long long v) {
    float2 r;
    asm("mov.b64 {%0, %1}, %2;" : "=f"(r.x), "=f"(r.y) : "l"(v));
    return r;
}
__device__ __forceinline__ float hsum2(unsigned long long v) {
    float2 p = unpack2(v);
    return p.x + p.y;
}

__device__ __forceinline__ void mma16816(float* c, const uint32_t* a, const uint32_t* b) {
    asm volatile(
        "mma.sync.aligned.m16n8k16.row.col.f32.bf16.bf16.f32 "
        "{%0,%1,%2,%3}, {%4,%5,%6,%7}, {%8,%9}, {%0,%1,%2,%3};"
        : "+f"(c[0]), "+f"(c[1]), "+f"(c[2]), "+f"(c[3])
        : "r"(a[0]), "r"(a[1]), "r"(a[2]), "r"(a[3]), "r"(b[0]), "r"(b[1]));
}
__device__ __forceinline__ void ldsm_x4(uint32_t& r0, uint32_t& r1, uint32_t& r2,
                                        uint32_t& r3, uint32_t addr) {
    asm volatile("ldmatrix.sync.aligned.m8n8.x4.shared.b16 {%0,%1,%2,%3}, [%4];"
                 : "=r"(r0), "=r"(r1), "=r"(r2), "=r"(r3) : "r"(addr));
}

// ---------------- rope table (512 distinct angles, full precision) ---------
__global__ void rope_table_kernel() {
    int t = threadIdx.x;           // 512 threads
    int kk = t >> 5, i = t & 31;
    float inv = expf(-(float)(2 * i) * (1.0f / 64.0f) * 9.210340371976184f);
    float sn, cs;
    sincosf((float)kk * inv, &sn, &cs);
    g_rope_c[t] = cs;
    g_rope_s[t] = sn;
}

// ---------------- bf16 split kernel: x -> hi + lo ----------------
__global__ __launch_bounds__(256) void split_kernel(const float* __restrict__ src,
                                                    __nv_bfloat16* __restrict__ hi,
                                                    __nv_bfloat16* __restrict__ lo,
                                                    int n4) {
    int i = blockIdx.x * 256 + threadIdx.x;
    if (i >= n4) return;
    float4 v = ((const float4*)src)[i];
    __nv_bfloat16 h0 = __float2bfloat16(v.x), h1 = __float2bfloat16(v.y);
    __nv_bfloat16 h2 = __float2bfloat16(v.z), h3 = __float2bfloat16(v.w);
    __nv_bfloat16 l0 = __float2bfloat16(v.x - __bfloat162float(h0));
    __nv_bfloat16 l1 = __float2bfloat16(v.y - __bfloat162float(h1));
    __nv_bfloat16 l2 = __float2bfloat16(v.z - __bfloat162float(h2));
    __nv_bfloat16 l3 = __float2bfloat16(v.w - __bfloat162float(h3));
    __nv_bfloat162 hA = {h0, h1}, hB = {h2, h3}, lA = {l0, l1}, lB = {l2, l3};
    uint2 hv = {*(uint32_t*)&hA, *(uint32_t*)&hB};
    uint2 lv = {*(uint32_t*)&lA, *(uint32_t*)&lB};
    *(uint2*)(hi + 4 * (size_t)i) = hv;
    *(uint2*)(lo + 4 * (size_t)i) = lv;
}

// ---------------- mma.sync GEMM + fused RoPE/scatter epilogue --------------
constexpr int SBg = 40;                           // bf16 row stride (80 bytes)
constexpr int TILE_SM = 128 * SBg;
constexpr int GEMM_SMEM = 2 * 4 * TILE_SM * 2;

__global__ __launch_bounds__(256, 1) void mma_gemm_kernel(
    const __nv_bfloat16* __restrict__ Ahi, const __nv_bfloat16* __restrict__ Alo,
    const __nv_bfloat16* __restrict__ Whi, const __nv_bfloat16* __restrict__ Wlo,
    float* __restrict__ outp, int qkv) {
    extern __shared__ __nv_bfloat16 smem[];
    const uint32_t sm0 = smem_u32_of(smem);

    const int t   = threadIdx.x;
    const int wid = t >> 5, l = t & 31;
    const int m0 = blockIdx.y * 128, n0 = blockIdx.x * 128;
    const int wm = (wid & 1) * 64, wn = (wid >> 1) * 32;

    const __nv_bfloat16* wh = Whi + (size_t)blockIdx.z * (Cc * Cc);
    const __nv_bfloat16* wl = Wlo + (size_t)blockIdx.z * (Cc * Cc);

    const __nv_bfloat16* srcs[4] = {Ahi + (size_t)m0 * 1024, Alo + (size_t)m0 * 1024,
                                    wh + (size_t)n0 * 1024,  wl + (size_t)n0 * 1024};

    float acc[4][4][4];
    #pragma unroll
    for (int i = 0; i < 4; i++)
        #pragma unroll
        for (int j = 0; j < 4; j++)
            #pragma unroll
            for (int r = 0; r < 4; r++) acc[i][j][r] = 0.f;

    auto issue = [&](int it, int s) {
        const int k0 = it * 32;
        #pragma unroll
        for (int x = 0; x < 8; x++) {
            int ci = x * 256 + t;
            int tile = ci >> 9, local = ci & 511;
            int row = local >> 2, ch = local & 3;
            const __nv_bfloat16* sp = srcs[tile] + (size_t)row * 1024 + k0 + ch * 8;
            uint32_t dp = sm0 + ((s * 4 + tile) * TILE_SM + row * SBg) * 2 + ch * 16;
            cp16(dp, sp);
        }
    };

    issue(0, 0);
    CP_COMMIT();

    const uint32_t a_lane = (uint32_t)(wm + (l & 15)) * 80 + ((l & 16) ? 16 : 0);
    const uint32_t b_lane = (uint32_t)(wn + l) * 80;

    for (int it = 0; it < 32; it++) {
        const int s = it & 1;
        if (it + 1 < 32) issue(it + 1, s ^ 1);
        CP_COMMIT();
        CP_WAIT1();
        __syncthreads();

        const uint32_t tAh = sm0 + (s * 4 + 0) * TILE_SM * 2;
        const uint32_t tAl = sm0 + (s * 4 + 1) * TILE_SM * 2;
        const uint32_t tBh = sm0 + (s * 4 + 2) * TILE_SM * 2;
        const uint32_t tBl = sm0 + (s * 4 + 3) * TILE_SM * 2;

        #pragma unroll
        for (int kk = 0; kk < 2; kk++) {
            const uint32_t kb = kk * 32;
            uint32_t bh[4][2], bl[4][2];
            ldsm_x4(bh[0][0], bh[1][0], bh[2][0], bh[3][0], tBh + b_lane + kb);
            ldsm_x4(bh[0][1], bh[1][1], bh[2][1], bh[3][1], tBh + b_lane + kb + 16);
            ldsm_x4(bl[0][0], bl[1][0], bl[2][0], bl[3][0], tBl + b_lane + kb);
            ldsm_x4(bl[0][1], bl[1][1], bl[2][1], bl[3][1], tBl + b_lane + kb + 16);
            #pragma unroll
            for (int i = 0; i < 4; i++) {
                const uint32_t ao = a_lane + (uint32_t)i * (16 * 80) + kb;
                uint32_t ah[4], al[4];
                ldsm_x4(ah[0], ah[1], ah[2], ah[3], tAh + ao);
                ldsm_x4(al[0], al[1], al[2], al[3], tAl + ao);
                #pragma unroll
                for (int j = 0; j < 4; j++) {
                    mma16816(acc[i][j], ah, bh[j]);
                    mma16816(acc[i][j], ah, bl[j]);
                    mma16816(acc[i][j], al, bh[j]);
                }
            }
        }
        __syncthreads();
    }

    if (qkv) {
        // fused RoPE (z=0,1) + scatter into scan layout (b,h,n,kk,d)
        const int zz = blockIdx.z;
        float* dst3 = (zz == 0) ? g_xq : (zz == 1) ? g_xk : g_xv;
        #pragma unroll
        for (int i = 0; i < 4; i++) {
            const int rbase = m0 + wm + i * 16 + (l >> 2);
            #pragma unroll
            for (int rr = 0; rr < 2; rr++) {
                const int r = rbase + rr * 8;
                const int b = r >> 11;
                const int n = (r & 2047) >> 4;
                const int kk = r & 15;
                #pragma unroll
                for (int j = 0; j < 4; j++) {
                    const int c0 = n0 + wn + j * 8 + (l & 3) * 2;
                    const int h = c0 >> 6, d = c0 & 63;
                    float vx = acc[i][j][rr * 2 + 0];
                    float vy = acc[i][j][rr * 2 + 1];
                    if (zz < 2) {
                        const int ti = kk * 32 + (d >> 1);
                        float cs = g_rope_c[ti], sn = g_rope_s[ti];
                        float e = vx * cs - vy * sn;
                        float o = vy * cs + vx * sn;
                        vx = e; vy = o;
                    }
                    size_t off = ((((size_t)b * NHc + h) * NCc + n) * Kc + kk) * HDc + d;
                    *(float2*)(dst3 + off) = make_float2(vx, vy);
                }
            }
        }
    } else {
        #pragma unroll
        for (int i = 0; i < 4; i++) {
            const int r0 = m0 + wm + i * 16 + (l >> 2);
            #pragma unroll
            for (int j = 0; j < 4; j++) {
                const int c0 = n0 + wn + j * 8 + (l & 3) * 2;
                float2 v0 = make_float2(acc[i][j][0], acc[i][j][1]);
                float2 v1 = make_float2(acc[i][j][2], acc[i][j][3]);
                *(float2*)(outp + (size_t)r0 * 1024 + c0)       = v0;
                *(float2*)(outp + (size_t)(r0 + 8) * 1024 + c0) = v1;
            }
        }
    }
}

// ---------------- prep: ttt_lr sigmoid only --------------------------------
__global__ __launch_bounds__(128) void prep_kernel(const float* __restrict__ hs,
                                                   const float* __restrict__ lrw,
                                                   const float* __restrict__ lrb) {
    const int m  = blockIdx.x;
    const int b  = m >> 11;
    const int l  = m & 2047;
    const int n  = l >> 4, kk = l & 15;
    __shared__ float xrow[1024];
    const int t = threadIdx.x;
    for (int i = t; i < 1024; i += 128) xrow[i] = hs[(size_t)m * 1024 + i];
    __syncthreads();
    const int wp = t >> 5, lane = t & 31;
    #pragma unroll
    for (int s = 0; s < 4; s++) {
        int h = wp * 4 + s;
        float acc = 0.f;
        for (int c = lane; c < 1024; c += 32) acc += xrow[c] * lrw[h * 1024 + c];
        acc = wsum(acc);
        if (lane == 0) {
            float z = acc + lrb[h];
            g_lr[(((size_t)b * NHc + h) * NCc + n) * Kc + kk] = fast_sigmoid(z);
        }
    }
}

// ---------------- scan kernel: 512 threads, f32x2-packed (R7 best) ---------
constexpr int O_W1T  = 0;                      // [256][68]  W1T[f][d]
constexpr int O_W2T  = O_W1T + 256 * 68;       // [64][260]  W2T[j][f]
constexpr int O_Z1   = O_W2T + 64 * 260;       // [16][260]  Z1, later X2bar
constexpr int O_X2   = O_Z1 + 16 * 260;        // [16][260]
constexpr int O_GZ1  = O_X2 + 16 * 260;        // [16][260]
constexpr int O_Z2   = O_GZ1 + 16 * 260;       // [16][68]
constexpr int O_Z2B  = O_Z2 + 16 * 68;         // [16][68]
constexpr int O_GZ2T = O_Z2B + 16 * 68;        // [64][20]  gZ2T[j][k]
constexpr int O_A1   = O_GZ2T + 64 * 20;       // [16][20]  (negated)
constexpr int O_A2   = O_A1 + 16 * 20;         // [16][20]  (negated)
constexpr int O_XBUF = O_A2 + 16 * 20;         // 2 stages x {xq,xk,xv} [16][68]
constexpr int XSTAGE = 3 * 16 * 68;            // 3264
constexpr int O_LRS  = O_XBUF + 2 * XSTAGE;    // [2][16]
constexpr int O_TOK  = O_LRS + 32;             // [16]
constexpr int O_B1   = O_TOK + 16;             // [256]
constexpr int O_B2   = O_B1 + 256;             // [64]
constexpr int O_GAM  = O_B2 + 64;              // [64]
constexpr int O_BET  = O_GAM + 64;             // [64]
constexpr int SCAN_SMEM_FLOATS = O_BET + 64;
constexpr int SCAN_SMEM_BYTES  = SCAN_SMEM_FLOATS * 4;   // 230592

__global__ __launch_bounds__(512, 1) void scan_kernel(
    const float* __restrict__ lti, const float* __restrict__ W1g,
    const float* __restrict__ b1g, const float* __restrict__ W2g,
    const float* __restrict__ b2g, const float* __restrict__ nw,
    const float* __restrict__ nb) {
    extern __shared__ float sm[];
    float* W1T  = sm + O_W1T;
    float* W2T  = sm + O_W2T;
    float* Z1   = sm + O_Z1;
    float* X2   = sm + O_X2;
    float* gZ1  = sm + O_GZ1;
    float* Z2   = sm + O_Z2;
    float* Z2b  = sm + O_Z2B;
    float* gZ2T = sm + O_GZ2T;
    float* A1   = sm + O_A1;
    float* A2   = sm + O_A2;
    float* tok64= sm + O_TOK;
    float* b1s  = sm + O_B1;
    float* b2s  = sm + O_B2;
    float* gam  = sm + O_GAM;
    float* bet  = sm + O_BET;

    const uint32_t sm_u = smem_u32_of(sm);
    const int t  = threadIdx.x;
    const int bh = blockIdx.x;
    const int hh = bh & 15;
    const int wp = t >> 5, lane = t & 31;

    for (int i = t; i < 16384; i += 512) {
        int d = i >> 8, f = i & 255;
        W1T[f * 68 + d] = W1g[hh * 16384 + d * 256 + f];
    }
    for (int i = t; i < 16384; i += 512) {
        int f = i >> 6, j = i & 63;
        W2T[j * 260 + f] = W2g[hh * 16384 + f * 64 + j];
    }
    if (t < 256) b1s[t] = b1g[hh * 256 + t];
    if (t < 64) { b2s[t] = b2g[hh * 64 + t]; gam[t] = nw[hh * 64 + t]; bet[t] = nb[hh * 64 + t]; }
    if (t < 16) tok64[t] = fmaxf(1.0f / (float)(t + 1) + lti[t], 0.0f) * (1.0f / 64.0f);

    auto issue_stage = [&](int nn) {
        const int st = nn & 1;
        const size_t cbn = ((size_t)bh * NCc + nn) * (Kc * HDc);
        const uint32_t xbase = sm_u + (O_XBUF + st * XSTAGE) * 4;
        for (int i = t; i < 772; i += 512) {
            if (i < 768) {
                int tile = i >> 8, local = i & 255;
                int row = local >> 4, c4 = local & 15;
                const float* srcb = (tile == 0) ? g_xq : (tile == 1) ? g_xk : g_xv;
                cp16(xbase + (tile * 1088 + row * 68 + c4 * 4) * 4,
                     srcb + cbn + row * 64 + c4 * 4);
            } else {
                int q = i - 768;
                cp16(sm_u + (O_LRS + st * 16 + q * 4) * 4,
                     g_lr + ((size_t)bh * NCc + nn) * Kc + q * 4);
            }
        }
    };

    issue_stage(0);
    CP_COMMIT();
    __syncthreads();

    const int colF = t & 255, halfF = t >> 8;
    const int k0F  = halfF * 8;
    const int jj64 = t & 63, rg = t >> 6;
    const int r0 = rg * 2;

    for (int n = 0; n < NCc; n++) {
        const int st = n & 1;
        float* xq_s = sm + O_XBUF + st * XSTAGE;
        float* xk_s = xq_s + 1088;
        float* xv_s = xk_s + 1088;
        float* lrs  = sm + O_LRS + st * 16;
        const size_t cb = ((size_t)bh * NCc + n) * (Kc * HDc);

        if (n + 1 < NCc) { issue_stage(n + 1); CP_COMMIT(); CP_WAIT1(); }
        else             { CP_WAIT0(); }
        __syncthreads();

        // ---- A: Z1 = xk@W1 + b1 ; X2 = gelu(Z1) ----
        {
            unsigned long long acc[8];
            #pragma unroll
            for (int k = 0; k < 8; k++) acc[k] = 0ull;
            const float* w1r = W1T + colF * 68;
            #pragma unroll 4
            for (int dg = 0; dg < 16; dg++) {
                ulonglong2 wv = *(const ulonglong2*)(w1r + dg * 4);
                #pragma unroll
                for (int k = 0; k < 8; k++) {
                    ulonglong2 xp = *(const ulonglong2*)(xk_s + (k0F + k) * 68 + dg * 4);
                    fma2(acc[k], xp.x, wv.x);
                    fma2(acc[k], xp.y, wv.y);
                }
            }
            float bv = b1s[colF];
            #pragma unroll
            for (int k = 0; k < 8; k++) {
                float s = hsum2(acc[k]) + bv;
                Z1[(k0F + k) * 260 + colF] = s;
                X2[(k0F + k) * 260 + colF] = gelu_f(s);
            }
        }
        __syncthreads();

        // ---- B: Z2 = X2@W2 + b2 ; A1 = -tril(tok*lr*(xq@xk^T + 1)) ----
        {
            unsigned long long a0 = 0ull, a1 = 0ull;
            const float* w2r = W2T + jj64 * 260;
            #pragma unroll 8
            for (int fg = 0; fg < 64; fg++) {
                ulonglong2 wv = *(const ulonglong2*)(w2r + fg * 4);
                ulonglong2 x0 = *(const ulonglong2*)(X2 + r0 * 260 + fg * 4);
                ulonglong2 x1 = *(const ulonglong2*)(X2 + (r0 + 1) * 260 + fg * 4);
                fma2(a0, x0.x, wv.x); fma2(a0, x0.y, wv.y);
                fma2(a1, x1.x, wv.x); fma2(a1, x1.y, wv.y);
            }
            float bv = b2s[jj64];
            Z2[r0 * 68 + jj64]       = hsum2(a0) + bv;
            Z2[(r0 + 1) * 68 + jj64] = hsum2(a1) + bv;

            if (t < 256) {
                const int ii = t >> 4, jj = t & 15;
                unsigned long long ac = 0ull;
                #pragma unroll 4
                for (int dg = 0; dg < 16; dg++) {
                    ulonglong2 qv = *(const ulonglong2*)(xq_s + ii * 68 + dg * 4);
                    ulonglong2 kv = *(const ulonglong2*)(xk_s + jj * 68 + dg * 4);
                    fma2(ac, qv.x, kv.x); fma2(ac, qv.y, kv.y);
                }
                float s = hsum2(ac);
                A1[ii * 20 + jj] = (jj <= ii) ? -(tok64[ii] * lrs[jj] * (s + 1.0f)) : 0.0f;
            }
        }
        __syncthreads();

        // ---- C: gZ2 = ln_fused_l2_bwd(Z2, xv-xk) -> gZ2T[j][k] ----
        {
            int k = wp;
            float z0 = Z2[k * 68 + lane], z1 = Z2[k * 68 + lane + 32];
            float mu = wsum(z0 + z1) * (1.0f / 64.0f);
            float d0 = z0 - mu, d1 = z1 - mu;
            float var = wsum(d0 * d0 + d1 * d1) * (1.0f / 64.0f);
            float rstd = rsqrtf(var + 1e-6f);
            float xh0 = d0 * rstd, xh1 = d1 * rstd;
            float g0 = gam[lane], g1 = gam[lane + 32];
            float be0 = bet[lane], be1 = bet[lane + 32];
            float tg0 = xv_s[k * 68 + lane] - xk_s[k * 68 + lane];
            float tg1 = xv_s[k * 68 + lane + 32] - xk_s[k * 68 + lane + 32];
            float go0 = (g0 * xh0 + be0 - tg0) * g0;
            float go1 = (g1 * xh1 + be1 - tg1) * g1;
            float sgo = wsum(go0 + go1);
            float sgx = wsum(go0 * xh0 + go1 * xh1);
            float cc = rstd * (1.0f / 64.0f);
            gZ2T[lane * 20 + k]        = (64.0f * go0 - sgo - xh0 * sgx) * cc;
            gZ2T[(lane + 32) * 20 + k] = (64.0f * go1 - sgo - xh1 * sgx) * cc;
        }
        __syncthreads();

        // ---- D: gZ1 = (gZ2 @ W2^T) * gelu_bwd(Z1) ----
        {
            unsigned long long acc[4] = {0ull, 0ull, 0ull, 0ull};
            const float* w2c = W2T + colF;
            #pragma unroll 8
            for (int j = 0; j < 64; j++) {
                unsigned long long wpr = bcast2(w2c[j * 260]);
                ulonglong2 ga = *(const ulonglong2*)(gZ2T + j * 20 + k0F);
                ulonglong2 gb = *(const ulonglong2*)(gZ2T + j * 20 + k0F + 4);
                fma2(acc[0], ga.x, wpr); fma2(acc[1], ga.y, wpr);
                fma2(acc[2], gb.x, wpr); fma2(acc[3], gb.y, wpr);
            }
            #pragma unroll
            for (int p = 0; p < 4; p++) {
                float2 g = unpack2(acc[p]);
                int row = k0F + 2 * p;
                gZ1[row * 260 + colF]       = g.x * gelu_bwd_f(Z1[row * 260 + colF]);
                gZ1[(row + 1) * 260 + colF] = g.y * gelu_bwd_f(Z1[(row + 1) * 260 + colF]);
            }
        }
        __syncthreads();

        // ---- E: X2bar = gelu(xq@W1 + b1 + A1neg@gZ1) -> Z1 buffer ----
        {
            unsigned long long acc[8];
            #pragma unroll
            for (int k = 0; k < 8; k++) acc[k] = 0ull;
            const float* w1r = W1T + colF * 68;
            #pragma unroll 4
            for (int dg = 0; dg < 16; dg++) {
                ulonglong2 wv = *(const ulonglong2*)(w1r + dg * 4);
                #pragma unroll
                for (int k = 0; k < 8; k++) {
                    ulonglong2 xp = *(const ulonglong2*)(xq_s + (k0F + k) * 68 + dg * 4);
                    fma2(acc[k], xp.x, wv.x);
                    fma2(acc[k], xp.y, wv.y);
                }
            }
            #pragma unroll
            for (int jp = 0; jp < 8; jp++) {
                unsigned long long gp = pack2f(gZ1[(2 * jp) * 260 + colF],
                                               gZ1[(2 * jp + 1) * 260 + colF]);
                #pragma unroll
                for (int k = 0; k < 8; k++) {
                    unsigned long long ap =
                        *(const unsigned long long*)(A1 + (k0F + k) * 20 + 2 * jp);
                    fma2(acc[k], ap, gp);
                }
            }
            float bv = b1s[colF];
            #pragma unroll
            for (int k = 0; k < 8; k++) {
                float s = hsum2(acc[k]) + bv;
                Z1[(k0F + k) * 260 + colF] = gelu_f(s);   // X2bar
            }
        }
        __syncthreads();

        // ---- F: A2 = -tril(tok*lr*(X2bar@X2^T + 1)) ----
        if (t < 256) {
            const int ii = t >> 4, jj = t & 15;
            unsigned long long ac = 0ull;
            #pragma unroll 8
            for (int fg = 0; fg < 64; fg++) {
                ulonglong2 zb = *(const ulonglong2*)(Z1 + ii * 260 + fg * 4);
                ulonglong2 xo = *(const ulonglong2*)(X2 + jj * 260 + fg * 4);
                fma2(ac, zb.x, xo.x); fma2(ac, zb.y, xo.y);
            }
            float s = hsum2(ac);
            A2[ii * 20 + jj] = (jj <= ii) ? -(tok64[ii] * lrs[jj] * (s + 1.0f)) : 0.0f;
        }
        __syncthreads();

        // ---- G: Z2b = X2bar@W2 + b2 + A2neg@gZ2 ----
        {
            unsigned long long a0 = 0ull, a1 = 0ull;
            const float* w2r = W2T + jj64 * 260;
            #pragma unroll 8
            for (int fg = 0; fg < 64; fg++) {
                ulonglong2 wv = *(const ulonglong2*)(w2r + fg * 4);
                ulonglong2 x0 = *(const ulonglong2*)(Z1 + r0 * 260 + fg * 4);
                ulonglong2 x1 = *(const ulonglong2*)(Z1 + (r0 + 1) * 260 + fg * 4);
                fma2(a0, x0.x, wv.x); fma2(a0, x0.y, wv.y);
                fma2(a1, x1.x, wv.x); fma2(a1, x1.y, wv.y);
            }
            #pragma unroll
            for (int jp = 0; jp < 8; jp++) {
                unsigned long long gp =
                    *(const unsigned long long*)(gZ2T + jj64 * 20 + 2 * jp);
                unsigned long long p0 =
                    *(const unsigned long long*)(A2 + r0 * 20 + 2 * jp);
                unsigned long long p1 =
                    *(const unsigned long long*)(A2 + (r0 + 1) * 20 + 2 * jp);
                fma2(a0, p0, gp);
                fma2(a1, p1, gp);
            }
            float bv = b2s[jj64];
            Z2b[r0 * 68 + jj64]       = hsum2(a0) + bv;
            Z2b[(r0 + 1) * 68 + jj64] = hsum2(a1) + bv;
        }
        __syncthreads();

        // ---- H: state updates ----
        {
            const float lef64 = tok64[15];
            {
                const int d0 = halfF * 32;
                float gc[16]; float sb = 0.f;
                #pragma unroll
                for (int k = 0; k < 16; k++) {
                    gc[k] = lef64 * lrs[k] * gZ1[k * 260 + colF];
                    sb += gc[k];
                }
                if (halfF == 0) b1s[colF] -= sb;
                unsigned long long gneg[16];
                #pragma unroll
                for (int k = 0; k < 16; k++) gneg[k] = bcast2(-gc[k]);
                float* w1r = W1T + colF * 68 + d0;
                #pragma unroll
                for (int dg = 0; dg < 8; dg++) {
                    ulonglong2 acc = *(const ulonglong2*)(w1r + dg * 4);
                    #pragma unroll
                    for (int k = 0; k < 16; k++) {
                        ulonglong2 xp = *(const ulonglong2*)(xk_s + k * 68 + d0 + dg * 4);
                        fma2(acc.x, xp.x, gneg[k]);
                        fma2(acc.y, xp.y, gneg[k]);
                    }
                    *(ulonglong2*)(w1r + dg * 4) = acc;
                }
            }
            {
                const int f0 = rg * 32;
                float hc[16]; float sb2 = 0.f;
                #pragma unroll
                for (int k = 0; k < 16; k++) {
                    hc[k] = lef64 * lrs[k] * gZ2T[jj64 * 20 + k];
                    sb2 += hc[k];
                }
                if (rg == 0) b2s[jj64] -= sb2;
                unsigned long long hneg[16];
                #pragma unroll
                for (int k = 0; k < 16; k++) hneg[k] = bcast2(-hc[k]);
                float* w2r = W2T + jj64 * 260 + f0;
                #pragma unroll
                for (int fg = 0; fg < 8; fg++) {
                    ulonglong2 acc = *(const ulonglong2*)(w2r + fg * 4);
                    #pragma unroll
                    for (int k = 0; k < 16; k++) {
                        ulonglong2 xp = *(const ulonglong2*)(X2 + k * 260 + f0 + fg * 4);
                        fma2(acc.x, xp.x, hneg[k]);
                        fma2(acc.y, xp.y, hneg[k]);
                    }
                    *(ulonglong2*)(w2r + fg * 4) = acc;
                }
            }

            // ---- I: out = xq + ln_fwd(Z2b) ----
            {
                int k = wp;
                float z0 = Z2b[k * 68 + lane], z1 = Z2b[k * 68 + lane + 32];
                float mu = wsum(z0 + z1) * (1.0f / 64.0f);
                float d0 = z0 - mu, d1 = z1 - mu;
                float var = wsum(d0 * d0 + d1 * d1) * (1.0f / 64.0f);
                float rstd = rsqrtf(var + 1e-6f);
                g_xqw[cb + k * 64 + lane] =
                    gam[lane] * d0 * rstd + bet[lane] + xq_s[k * 68 + lane];
                g_xqw[cb + k * 64 + lane + 32] =
                    gam[lane + 32] * d1 * rstd + bet[lane + 32] + xq_s[k * 68 + lane + 32];
            }
        }
        __syncthreads();
    }
}

// ---------------- post layernorm over C (fused bf16 split output) ----------
__global__ __launch_bounds__(256) void postln_kernel(const float* __restrict__ pw,
                                                     const float* __restrict__ pb,
                                                     __nv_bfloat16* __restrict__ ahi,
                                                     __nv_bfloat16* __restrict__ alo) {
    const int m = blockIdx.x;
    const int b = m >> 11, l = m & 2047;
    const int n = l >> 4, kk = l & 15;
    __shared__ float row[1024];
    __shared__ float red[18];
    const int t = threadIdx.x;
    for (int i = t; i < 1024; i += 256) {
        int h = i >> 6, d = i & 63;
        row[i] = g_xqw[((((size_t)b * NHc + h) * NCc + n) * Kc + kk) * HDc + d];
    }
    __syncthreads();
    float s = 0.f, ss = 0.f;
    for (int i = t; i < 1024; i += 256) { float v = row[i]; s += v; ss += v * v; }
    s = wsum(s); ss = wsum(ss);
    const int wp = t >> 5, lane = t & 31;
    if (lane == 0) { red[wp] = s; red[8 + wp] = ss; }
    __syncthreads();
    if (t == 0) {
        float S = 0.f, SS = 0.f;
        for (int w = 0; w < 8; w++) { S += red[w]; SS += red[8 + w]; }
        float mu = S * (1.0f / 1024.0f);
        red[16] = mu;
        red[17] = rsqrtf(SS * (1.0f / 1024.0f) - mu * mu + 1e-6f);
    }
    __syncthreads();
    float mu = red[16], rstd = red[17];
    for (int i = t; i < 1024; i += 256) {
        float v = pw[i] * (row[i] - mu) * rstd + pb[i];
        __nv_bfloat16 hv = __float2bfloat16(v);
        ahi[(size_t)m * 1024 + i] = hv;
        alo[(size_t)m * 1024 + i] = __float2bfloat16(v - __bfloat162float(hv));
    }
}

// ---------------- launch (reordered: QKV GEMM is launch index 5 for ncu) ----
extern "C" void kernel_launch(void* const* d_in, const int* in_sizes, int n_in,
                              void* d_out, int out_size) {
    (void)in_sizes; (void)n_in; (void)out_size;
    const float* hs  = (const float*)d_in[0];
    const float* wq  = (const float*)d_in[1];
    const float* wk  = (const float*)d_in[2];
    const float* wv  = (const float*)d_in[3];
    const float* wo  = (const float*)d_in[4];
    const float* lti = (const float*)d_in[5];
    const float* lrw = (const float*)d_in[6];
    const float* lrb = (const float*)d_in[7];
    const float* nw  = (const float*)d_in[8];
    const float* nb  = (const float*)d_in[9];
    const float* pw  = (const float*)d_in[10];
    const float* pb  = (const float*)d_in[11];
    const float* W1g = (const float*)d_in[12];
    const float* b1g = (const float*)d_in[13];
    const float* W2g = (const float*)d_in[14];
    const float* b2g = (const float*)d_in[15];
    float* out = (float*)d_out;

    cudaFuncSetAttribute(scan_kernel, cudaFuncAttributeMaxDynamicSharedMemorySize,
                         SCAN_SMEM_BYTES);
    cudaFuncSetAttribute(mma_gemm_kernel, cudaFuncAttributeMaxDynamicSharedMemorySize,
                         GEMM_SMEM);

    void *p_ahi, *p_alo, *p_whi, *p_wlo;
    cudaGetSymbolAddress(&p_ahi, g_ahi);
    cudaGetSymbolAddress(&p_alo, g_alo);
    cudaGetSymbolAddress(&p_whi, g_whi);
    cudaGetSymbolAddress(&p_wlo, g_wlo);
    __nv_bfloat16* ahi = (__nv_bfloat16*)p_ahi;
    __nv_bfloat16* alo = (__nv_bfloat16*)p_alo;
    __nv_bfloat16* whi = (__nv_bfloat16*)p_whi;
    __nv_bfloat16* wlo = (__nv_bfloat16*)p_wlo;

    const int NA4 = (Bc * Lc * Cc) / 4;
    const int NW4 = (Cc * Cc) / 4;

    // idx 0: A operand split
    split_kernel<<<(NA4 + 255) / 256, 256>>>(hs, ahi, alo, NA4);
    // idx 1-3: Q/K/V weight splits
    split_kernel<<<(NW4 + 255) / 256, 256>>>(wq, whi + 0 * Cc * Cc, wlo + 0 * Cc * Cc, NW4);
    split_kernel<<<(NW4 + 255) / 256, 256>>>(wk, whi + 1 * Cc * Cc, wlo + 1 * Cc * Cc, NW4);
    split_kernel<<<(NW4 + 255) / 256, 256>>>(wv, whi + 2 * Cc * Cc, wlo + 2 * Cc * Cc, NW4);
    // idx 4: rope table (needed by QKV GEMM epilogue)
    rope_table_kernel<<<1, 512>>>();
    // idx 5: QKV GEMM  <-- ncu -s 5 -c 1 profiles this launch
    mma_gemm_kernel<<<dim3(8, 64, 3), 256, GEMM_SMEM>>>(ahi, alo, whi, wlo, nullptr, 1);
    // idx 6: output-proj weight split
    split_kernel<<<(NW4 + 255) / 256, 256>>>(wo, whi + 3 * Cc * Cc, wlo + 3 * Cc * Cc, NW4);
    // idx 7: ttt_lr prep
    prep_kernel<<<Mtok, 128>>>(hs, lrw, lrb);
    // idx 8: scan
    scan_kernel<<<Bc * NHc, 512, SCAN_SMEM_BYTES>>>(lti, W1g, b1g, W2g, b2g, nw, nb);
    // idx 9: post layernorm (+ bf16 split of h2)
    postln_kernel<<<Mtok, 256>>>(pw, pb, ahi, alo);
    // idx 10: output projection GEMM
    mma_gemm_kernel<<<dim3(8, 64, 1), 256, GEMM_SMEM>>>(ahi, alo,
                                                        whi + 3 * Cc * Cc, wlo + 3 * Cc * Cc,
                                                        out, 0);
}